// round 7
// baseline (speedup 1.0000x reference)
#include <cuda_runtime.h>
#include <math.h>

#define HCH  512
#define NST  64
#define BS   8
#define LSEQ 2048
#define NFFT 4096
#define SIDX(i) ((i) + ((i) >> 4))
#define SPAD (NFFT + (NFFT >> 4))   // 4352 float2 = 34816 B

// per-channel spectrum, natural-position layout: kf[p] = FFT output at position p
// (holding frequency brev12(p))
__device__ float2 d_Kf[(size_t)HCH * NFFT];

// W16^m = exp(-2*pi*i*m/16), m=0..7
__constant__ float2 C16[8] = {
    { 1.0f,           0.0f},
    { 0.92387953251f, -0.38268343236f},
    { 0.70710678119f, -0.70710678119f},
    { 0.38268343236f, -0.92387953251f},
    { 0.0f,          -1.0f},
    {-0.38268343236f, -0.92387953251f},
    {-0.70710678119f, -0.70710678119f},
    {-0.92387953251f, -0.38268343236f},
};
// W8^m = exp(-2*pi*i*m/8), m=0..3
__constant__ float2 C8[4] = {
    { 1.0f,           0.0f},
    { 0.70710678119f, -0.70710678119f},
    { 0.0f,          -1.0f},
    {-0.70710678119f, -0.70710678119f},
};
// brev3 lookup
__constant__ int BR8[8] = {0, 4, 2, 6, 1, 5, 3, 7};

__device__ __forceinline__ float2 cmul(float2 a, float2 b) {
    return make_float2(fmaf(a.x, b.x, -a.y * b.y), fmaf(a.x, b.y, a.y * b.x));
}
__device__ __forceinline__ float2 cmulj(float2 a, float2 b) {   // a * conj(b)
    return make_float2(fmaf(a.x, b.x, a.y * b.y), fmaf(a.y, b.x, -a.x * b.y));
}
__device__ __forceinline__ float2 cadd(float2 a, float2 b) { return make_float2(a.x + b.x, a.y + b.y); }
__device__ __forceinline__ float2 csub(float2 a, float2 b) { return make_float2(a.x - b.x, a.y - b.y); }

// W4096^j = exp(-2*pi*i*j/4096), exact-argument via sincospif
__device__ __forceinline__ float2 tw4096(int j) {
    float s, c;
    sincospif((float)j * (1.0f / 2048.0f), &s, &c);
    return make_float2(c, -s);
}
__device__ __forceinline__ float2 tw4096c(int j) {
    float s, c;
    sincospif((float)j * (1.0f / 2048.0f), &s, &c);
    return make_float2(c, s);
}

// ---------------------------------------------------------------------------
// 16-point register FFT (spec kernel): 3 passes = full radix-2 DIF,
// position p ends holding frequency brev12(p).
// ---------------------------------------------------------------------------
__device__ __forceinline__ void fwd16(float2* v, float2 w1) {
    float2 w2 = cmul(w1, w1), w4 = cmul(w2, w2), w8 = cmul(w4, w4);
#pragma unroll
    for (int j = 0; j < 8; j++) {
        float2 tw = cmul(w1, C16[j]);
        float2 a = v[j], bb = v[j + 8];
        v[j] = cadd(a, bb);
        v[j + 8] = cmul(csub(a, bb), tw);
    }
#pragma unroll
    for (int g = 0; g < 16; g += 8)
#pragma unroll
        for (int j = 0; j < 4; j++) {
            float2 tw = cmul(w2, C16[2 * j]);
            float2 a = v[g + j], bb = v[g + j + 4];
            v[g + j] = cadd(a, bb);
            v[g + j + 4] = cmul(csub(a, bb), tw);
        }
#pragma unroll
    for (int g = 0; g < 16; g += 4)
#pragma unroll
        for (int j = 0; j < 2; j++) {
            float2 tw = cmul(w4, C16[4 * j]);
            float2 a = v[g + j], bb = v[g + j + 2];
            v[g + j] = cadd(a, bb);
            v[g + j + 2] = cmul(csub(a, bb), tw);
        }
#pragma unroll
    for (int g = 0; g < 16; g += 2) {
        float2 a = v[g], bb = v[g + 1];
        v[g] = cadd(a, bb);
        v[g + 1] = cmul(csub(a, bb), w8);
    }
}

// ---------------------------------------------------------------------------
// 8-point register FFT (conv kernel): radix-8 = 3 radix-2 DIF stages.
// ---------------------------------------------------------------------------
__device__ __forceinline__ void fwd8(float2* v, float2 w1) {
    float2 w2 = cmul(w1, w1), w4 = cmul(w2, w2);
#pragma unroll
    for (int j = 0; j < 4; j++) {
        float2 tw = cmul(w1, C8[j]);
        float2 a = v[j], bb = v[j + 4];
        v[j] = cadd(a, bb);
        v[j + 4] = cmul(csub(a, bb), tw);
    }
#pragma unroll
    for (int g = 0; g < 8; g += 4)
#pragma unroll
        for (int j = 0; j < 2; j++) {
            float2 tw = cmul(w2, C8[2 * j]);
            float2 a = v[g + j], bb = v[g + j + 2];
            v[g + j] = cadd(a, bb);
            v[g + j + 2] = cmul(csub(a, bb), tw);
        }
#pragma unroll
    for (int g = 0; g < 8; g += 2) {
        float2 a = v[g], bb = v[g + 1];
        v[g] = cadd(a, bb);
        v[g + 1] = cmul(csub(a, bb), w4);
    }
}

__device__ __forceinline__ void inv8(float2* v, float2 w1) {
    float2 c1 = make_float2(w1.x, -w1.y);
    float2 c2 = cmul(c1, c1), c4 = cmul(c2, c2);
#pragma unroll
    for (int g = 0; g < 8; g += 2) {
        float2 tb = cmul(v[g + 1], c4);
        float2 a = v[g];
        v[g] = cadd(a, tb);
        v[g + 1] = csub(a, tb);
    }
#pragma unroll
    for (int g = 0; g < 8; g += 4)
#pragma unroll
        for (int j = 0; j < 2; j++) {
            float2 tw = cmulj(c2, C8[2 * j]);
            float2 tb = cmul(v[g + j + 2], tw);
            float2 a = v[g + j];
            v[g + j] = cadd(a, tb);
            v[g + j + 2] = csub(a, tb);
        }
#pragma unroll
    for (int j = 0; j < 4; j++) {
        float2 tw = cmulj(c1, C8[j]);
        float2 tb = cmul(v[j + 4], tw);
        float2 a = v[j];
        v[j] = cadd(a, tb);
        v[j + 4] = csub(a, tb);
    }
}

// ---------------------------------------------------------------------------
// Kernel B: per-channel spectral kernel build (conjugate-pair Cauchy loop).
// ---------------------------------------------------------------------------
__global__ void __launch_bounds__(256, 2) kernel_spec(
        const float* __restrict__ Lr, const float* __restrict__ Li,
        const float* __restrict__ Pr, const float* __restrict__ Pi,
        const float* __restrict__ Br, const float* __restrict__ Bi,
        const float* __restrict__ Cr, const float* __restrict__ Ci,
        const float* __restrict__ logdt) {
    const int h   = blockIdx.x;
    const int tid = threadIdx.x;

    __shared__ float2 lam[NST], w00[NST], w01[NST], w10[NST];
    __shared__ float  w11[NST];
    extern __shared__ float2 x[];   // SPAD float2

    if (tid < NST) {
        int n = tid;
        lam[n] = make_float2(Lr[n], Li[n]);
        float2 P  = make_float2(Pr[n], Pi[n]);
        float2 Bv = make_float2(Br[n], Bi[n]);
        float2 Cc = make_float2(Cr[h * NST + n], -Ci[h * NST + n]);
        w00[n] = cmul(Cc, Bv);
        w01[n] = cmul(Cc, P);
        float2 Qc = make_float2(P.x, -P.y);
        w10[n] = cmul(Qc, Bv);
        w11[n] = P.x * P.x + P.y * P.y;
    }
    __syncthreads();

    const float dt = expf(logdt[h]);
    const float g0 = 2.0f / dt;

    // ---- at_roots into x[0..2047] (natural order), pairing l with 2048-l ----
    for (int l = tid; l < 1024; l += blockDim.x) {
        float ss, cc;
        sincospif((float)l * (1.0f / 1024.0f), &ss, &cc);
        float2 om = make_float2(cc, -ss);
        float2 den = make_float2(1.f + om.x, om.y);
        float2 num = make_float2(1.f - om.x, -om.y);
        float idl  = __fdividef(1.f, den.x * den.x + den.y * den.y);
        float2 c2  = make_float2(2.f * den.x * idl, -2.f * den.y * idl);
        float2 gf  = cmul(num, make_float2(den.x, -den.y));
        float2 g   = make_float2(g0 * gf.x * idl, g0 * gf.y * idl);

        float2 a00 = {0.f, 0.f}, a01 = {0.f, 0.f}, a10 = {0.f, 0.f}, a11 = {0.f, 0.f};
        float2 b00 = {0.f, 0.f}, b01 = {0.f, 0.f}, b10 = {0.f, 0.f}, b11 = {0.f, 0.f};
#pragma unroll 4
        for (int n = 0; n < NST; n++) {
            float dx  = g.x - lam[n].x;
            float dy  = g.y - lam[n].y;
            float inv = __fdividef(1.f, dx * dx + dy * dy);
            float2 r  = make_float2(dx * inv, -dy * inv);     // 1/(g - lam_n)
            a00 = cadd(a00, cmul(w00[n], r));
            a01 = cadd(a01, cmul(w01[n], r));
            a10 = cadd(a10, cmul(w10[n], r));
            a11.x = fmaf(w11[n], r.x, a11.x);
            a11.y = fmaf(w11[n], r.y, a11.y);
            int m = NST - 1 - n;
            float2 rc = make_float2(r.x, -r.y);
            b00 = cadd(b00, cmul(w00[m], rc));
            b01 = cadd(b01, cmul(w01[m], rc));
            b10 = cadd(b10, cmul(w10[m], rc));
            b11.x = fmaf(w11[m], rc.x, b11.x);
            b11.y = fmaf(w11[m], rc.y, b11.y);
        }
        {   // A[l]
            float2 onep = make_float2(1.f + a11.x, a11.y);
            float  ip   = __fdividef(1.f, onep.x * onep.x + onep.y * onep.y);
            float2 invd = make_float2(onep.x * ip, -onep.y * ip);
            float2 t2   = cmul(cmul(a01, a10), invd);
            x[SIDX(l)]  = cmul(c2, csub(a00, t2));
        }
        if (l != 0) {   // A[2048-l], c2' = conj(c2)
            float2 c2c  = make_float2(c2.x, -c2.y);
            float2 onep = make_float2(1.f + b11.x, b11.y);
            float  ip   = __fdividef(1.f, onep.x * onep.x + onep.y * onep.y);
            float2 invd = make_float2(onep.x * ip, -onep.y * ip);
            float2 t2   = cmul(cmul(b01, b10), invd);
            x[SIDX(2048 - l)] = cmul(c2c, csub(b00, t2));
        }
    }
    if (tid == 0) {
        // l = 1024: omega = -1, analytic limit: at -> dt * sum(w00) / 2
        float2 s = make_float2(0.f, 0.f);
        for (int n = 0; n < NST; n++) s = cadd(s, w00[n]);
        x[SIDX(1024)] = make_float2(0.5f * dt * s.x, 0.5f * dt * s.y);
    }
    __syncthreads();

    // ---- inverse FFT 2048 (radix-2 DIF, conj tw): natural -> bit-reversed ----
    {
        int step = 2;
        for (int mh = 1024; mh >= 1; mh >>= 1, step <<= 1) {
            for (int t = tid; t < 1024; t += blockDim.x) {
                int k  = t & (mh - 1);
                int i0 = 2 * t - k, i1 = i0 + mh;
                float2 a = x[SIDX(i0)], b = x[SIDX(i1)];
                x[SIDX(i0)] = cadd(a, b);
                x[SIDX(i1)] = cmul(csub(a, b), tw4096c(k * step));
            }
            __syncthreads();
        }
    }
    // bit-reverse (11-bit) to natural order
    for (int i = tid; i < 2048; i += blockDim.x) {
        int r = __brev(i) >> 21;
        if (r > i) { float2 t = x[SIDX(i)]; x[SIDX(i)] = x[SIDX(r)]; x[SIDX(r)] = t; }
    }
    __syncthreads();
    const float sc = 1.0f / 2048.0f;
    for (int i = tid; i < 2048; i += blockDim.x) {
        float2 t = x[SIDX(i)];
        x[SIDX(i)] = make_float2(t.x * sc, 0.f);
    }
    for (int i = 2048 + tid; i < NFFT; i += blockDim.x) x[SIDX(i)] = make_float2(0.f, 0.f);
    __syncthreads();

    // ---- forward FFT 4096: 3 register-radix-16 passes ----
    float2 v[16];
#pragma unroll
    for (int j = 0; j < 16; j++) v[j] = x[SIDX(tid + 256 * j)];
    fwd16(v, tw4096(tid));
#pragma unroll
    for (int j = 0; j < 16; j++) x[SIDX(tid + 256 * j)] = v[j];
    __syncthreads();

    const int base2 = ((tid >> 4) << 8) + (tid & 15);
#pragma unroll
    for (int j = 0; j < 16; j++) v[j] = x[SIDX(base2 + 16 * j)];
    fwd16(v, tw4096((tid & 15) << 4));
#pragma unroll
    for (int j = 0; j < 16; j++) x[SIDX(base2 + 16 * j)] = v[j];
    __syncthreads();

#pragma unroll
    for (int j = 0; j < 16; j++) v[j] = x[SIDX(16 * tid + j)];
    fwd16(v, make_float2(1.f, 0.f));

    // store by NATURAL POSITION index: kf[p] = value at position p
    // (contiguous 128B per thread)
    float2* kf = d_Kf + (size_t)h * NFFT;
#pragma unroll
    for (int j = 0; j < 16; j++) kf[16 * tid + j] = v[j];
}

// ---------------------------------------------------------------------------
// Kernel C: packed two-channel FFT convolution + skip.
// 512 threads, radix-8, 4 passes. v[8] -> ~64 regs -> 2 CTAs/SM, 32 warps.
// ---------------------------------------------------------------------------
__global__ void __launch_bounds__(512, 2) kernel_conv(
        const float* __restrict__ u, const float* __restrict__ D,
        float* __restrict__ y) {
    const int hp = blockIdx.x;                 // channel pair: (2hp, 2hp+1)
    const int b  = blockIdx.y;
    const int t  = threadIdx.x;
    extern __shared__ float2 x[];   // SPAD float2

    const float2* uf2 = (const float2*)(u + (size_t)b * LSEQ * HCH) + hp;
    float2 v[8];
#pragma unroll
    for (int j = 0; j < 4; j++)
        v[j] = uf2[(size_t)(t + 512 * j) * (HCH / 2)];
#pragma unroll
    for (int j = 4; j < 8; j++) v[j] = make_float2(0.f, 0.f);

    // ---- forward 4096: 4 radix-8 passes ----
    const float2 w1 = tw4096(t);
    fwd8(v, w1);
#pragma unroll
    for (int j = 0; j < 8; j++) x[SIDX(t + 512 * j)] = v[j];
    __syncthreads();

    const int s2 = t & 63;
    const int p2base = ((t >> 6) << 9) + s2;
    const float2 wp2 = tw4096(8 * s2);
#pragma unroll
    for (int j = 0; j < 8; j++) v[j] = x[SIDX(p2base + 64 * j)];
    fwd8(v, wp2);
#pragma unroll
    for (int j = 0; j < 8; j++) x[SIDX(p2base + 64 * j)] = v[j];
    __syncthreads();

    const int s3 = t & 7;
    const int p3base = ((t >> 3) << 6) + s3;
    const float2 wp3 = tw4096(64 * s3);
#pragma unroll
    for (int j = 0; j < 8; j++) v[j] = x[SIDX(p3base + 8 * j)];
    fwd8(v, wp3);
#pragma unroll
    for (int j = 0; j < 8; j++) x[SIDX(p3base + 8 * j)] = v[j];
    __syncthreads();

#pragma unroll
    for (int j = 0; j < 8; j++) v[j] = x[SIDX(8 * t + j)];
    fwd8(v, make_float2(1.f, 0.f));
    // v[j] = Z at position p = 8t+j, frequency k = brev12(p) = (brev3(j)<<9)|brev9(t)

    // ---- natural-frequency exchange for Hermitian split ----
    const int rb9 = __brev(t) >> 23;           // brev9(t)
    __syncthreads();
#pragma unroll
    for (int j = 0; j < 8; j++)
        x[SIDX((BR8[j] << 9) | rb9)] = v[j];
    __syncthreads();

    // S(k) = Z(k)*(Ka+Kb)/2 + conj(Z(N-k))*(Ka-Kb)/2
    const float2* kfa = d_Kf + (size_t)(2 * hp) * NFFT;
    const float2* kfb = d_Kf + (size_t)(2 * hp + 1) * NFFT;
#pragma unroll
    for (int j = 0; j < 8; j++) {
        int k  = (BR8[j] << 9) | rb9;
        int km = (NFFT - k) & (NFFT - 1);
        float2 Zm = x[SIDX(km)];
        float2 Ka = kfa[8 * t + j];
        float2 Kb = kfb[8 * t + j];
        float2 Kp = make_float2(0.5f * (Ka.x + Kb.x), 0.5f * (Ka.y + Kb.y));
        float2 Km = make_float2(0.5f * (Ka.x - Kb.x), 0.5f * (Ka.y - Kb.y));
        float2 Zmc = make_float2(Zm.x, -Zm.y);
        v[j] = cadd(cmul(v[j], Kp), cmul(Zmc, Km));
    }
    __syncthreads();                            // before overwriting x

    // ---- inverse 4096: 4 radix-8 passes (reverse order) ----
    inv8(v, make_float2(1.f, 0.f));
#pragma unroll
    for (int j = 0; j < 8; j++) x[SIDX(8 * t + j)] = v[j];
    __syncthreads();

#pragma unroll
    for (int j = 0; j < 8; j++) v[j] = x[SIDX(p3base + 8 * j)];
    inv8(v, wp3);
#pragma unroll
    for (int j = 0; j < 8; j++) x[SIDX(p3base + 8 * j)] = v[j];
    __syncthreads();

#pragma unroll
    for (int j = 0; j < 8; j++) v[j] = x[SIDX(p2base + 64 * j)];
    inv8(v, wp2);
#pragma unroll
    for (int j = 0; j < 8; j++) x[SIDX(p2base + 64 * j)] = v[j];
    __syncthreads();

#pragma unroll
    for (int j = 0; j < 8; j++) v[j] = x[SIDX(t + 512 * j)];
    inv8(v, w1);
    // v[j] = y_a + i*y_b at time l = t + 512j (times NFFT); only j<4 valid

    const float Da  = D[2 * hp];
    const float Db  = D[2 * hp + 1];
    const float inv = 1.0f / (float)NFFT;
    float2* yf2 = (float2*)(y + (size_t)b * LSEQ * HCH) + hp;
#pragma unroll
    for (int j = 0; j < 4; j++) {
        float2 uu = uf2[(size_t)(t + 512 * j) * (HCH / 2)];
        float2 out;
        out.x = fmaf(v[j].x, inv, uu.x * Da);
        out.y = fmaf(v[j].y, inv, uu.y * Db);
        yf2[(size_t)(t + 512 * j) * (HCH / 2)] = out;
    }
}

// ---------------------------------------------------------------------------
extern "C" void kernel_launch(void* const* d_in, const int* in_sizes, int n_in,
                              void* d_out, int out_size) {
    const float* u   = (const float*)d_in[0];
    const float* Lr  = (const float*)d_in[1];
    const float* Li  = (const float*)d_in[2];
    const float* Pr  = (const float*)d_in[3];
    const float* Pi  = (const float*)d_in[4];
    const float* Br  = (const float*)d_in[5];
    const float* Bi  = (const float*)d_in[6];
    const float* Cr  = (const float*)d_in[7];
    const float* Ci  = (const float*)d_in[8];
    const float* ldt = (const float*)d_in[9];
    const float* D   = (const float*)d_in[10];
    float* y = (float*)d_out;

    const size_t smem = (size_t)SPAD * sizeof(float2);   // 34816 B

    kernel_spec<<<HCH, 256, smem>>>(Lr, Li, Pr, Pi, Br, Bi, Cr, Ci, ldt);
    kernel_conv<<<dim3(HCH / 2, BS), 512, smem>>>(u, D, y);
}

// round 9
// speedup vs baseline: 1.1000x; 1.1000x over previous
#include <cuda_runtime.h>
#include <math.h>

#define HCH  512
#define NST  64
#define BS   8
#define LSEQ 2048
#define NFFT 4096
#define SIDX(i) ((i) + ((i) >> 4))
#define SPAD (NFFT + (NFFT >> 4))   // 4352 float2 = 34816 B

// per-channel spectrum, layout [h][j*256 + t] holding bit-rev position p=16t+j
__device__ float2 d_Kf[(size_t)HCH * NFFT];

// W16^m = exp(-2*pi*i*m/16), m=0..7
__constant__ float2 C16[8] = {
    { 1.0f,           0.0f},
    { 0.92387953251f, -0.38268343236f},
    { 0.70710678119f, -0.70710678119f},
    { 0.38268343236f, -0.92387953251f},
    { 0.0f,          -1.0f},
    {-0.38268343236f, -0.92387953251f},
    {-0.70710678119f, -0.70710678119f},
    {-0.92387953251f, -0.38268343236f},
};

__device__ __forceinline__ float2 cmul(float2 a, float2 b) {
    return make_float2(fmaf(a.x, b.x, -a.y * b.y), fmaf(a.x, b.y, a.y * b.x));
}
__device__ __forceinline__ float2 cmulj(float2 a, float2 b) {   // a * conj(b)
    return make_float2(fmaf(a.x, b.x, a.y * b.y), fmaf(a.y, b.x, -a.x * b.y));
}
__device__ __forceinline__ float2 cadd(float2 a, float2 b) { return make_float2(a.x + b.x, a.y + b.y); }
__device__ __forceinline__ float2 csub(float2 a, float2 b) { return make_float2(a.x - b.x, a.y - b.y); }

// W4096^j = exp(-2*pi*i*j/4096), exact-argument via sincospif
__device__ __forceinline__ float2 tw4096(int j) {
    float s, c;
    sincospif((float)j * (1.0f / 2048.0f), &s, &c);
    return make_float2(c, -s);
}
__device__ __forceinline__ float2 tw4096c(int j) {
    float s, c;
    sincospif((float)j * (1.0f / 2048.0f), &s, &c);
    return make_float2(c, s);
}

// ---------------------------------------------------------------------------
// 16-point register FFT blocks (3 passes = full radix-2 DIF; position p ends
// holding frequency brev12(p)).
// ---------------------------------------------------------------------------
__device__ __forceinline__ void fwd16(float2* v, float2 w1) {
    float2 w2 = cmul(w1, w1), w4 = cmul(w2, w2), w8 = cmul(w4, w4);
#pragma unroll
    for (int j = 0; j < 8; j++) {
        float2 tw = cmul(w1, C16[j]);
        float2 a = v[j], bb = v[j + 8];
        v[j] = cadd(a, bb);
        v[j + 8] = cmul(csub(a, bb), tw);
    }
#pragma unroll
    for (int g = 0; g < 16; g += 8)
#pragma unroll
        for (int j = 0; j < 4; j++) {
            float2 tw = cmul(w2, C16[2 * j]);
            float2 a = v[g + j], bb = v[g + j + 4];
            v[g + j] = cadd(a, bb);
            v[g + j + 4] = cmul(csub(a, bb), tw);
        }
#pragma unroll
    for (int g = 0; g < 16; g += 4)
#pragma unroll
        for (int j = 0; j < 2; j++) {
            float2 tw = cmul(w4, C16[4 * j]);
            float2 a = v[g + j], bb = v[g + j + 2];
            v[g + j] = cadd(a, bb);
            v[g + j + 2] = cmul(csub(a, bb), tw);
        }
#pragma unroll
    for (int g = 0; g < 16; g += 2) {
        float2 a = v[g], bb = v[g + 1];
        v[g] = cadd(a, bb);
        v[g + 1] = cmul(csub(a, bb), w8);
    }
}

__device__ __forceinline__ void inv16(float2* v, float2 w1) {
    float2 c1 = make_float2(w1.x, -w1.y);
    float2 c2 = cmul(c1, c1), c4 = cmul(c2, c2), c8 = cmul(c4, c4);
#pragma unroll
    for (int g = 0; g < 16; g += 2) {
        float2 tb = cmul(v[g + 1], c8);
        float2 a = v[g];
        v[g] = cadd(a, tb);
        v[g + 1] = csub(a, tb);
    }
#pragma unroll
    for (int g = 0; g < 16; g += 4)
#pragma unroll
        for (int j = 0; j < 2; j++) {
            float2 tw = cmulj(c4, C16[4 * j]);
            float2 tb = cmul(v[g + j + 2], tw);
            float2 a = v[g + j];
            v[g + j] = cadd(a, tb);
            v[g + j + 2] = csub(a, tb);
        }
#pragma unroll
    for (int g = 0; g < 16; g += 8)
#pragma unroll
        for (int j = 0; j < 4; j++) {
            float2 tw = cmulj(c2, C16[2 * j]);
            float2 tb = cmul(v[g + j + 4], tw);
            float2 a = v[g + j];
            v[g + j] = cadd(a, tb);
            v[g + j + 4] = csub(a, tb);
        }
#pragma unroll
    for (int j = 0; j < 8; j++) {
        float2 tw = cmulj(c1, C16[j]);
        float2 tb = cmul(v[j + 8], tw);
        float2 a = v[j];
        v[j] = cadd(a, tb);
        v[j + 8] = csub(a, tb);
    }
}

// ---------------------------------------------------------------------------
// Kernel B: per-channel spectral kernel build (R5-exact configuration).
// ---------------------------------------------------------------------------
__global__ void __launch_bounds__(256) kernel_spec(
        const float* __restrict__ Lr, const float* __restrict__ Li,
        const float* __restrict__ Pr, const float* __restrict__ Pi,
        const float* __restrict__ Br, const float* __restrict__ Bi,
        const float* __restrict__ Cr, const float* __restrict__ Ci,
        const float* __restrict__ logdt) {
    const int h   = blockIdx.x;
    const int tid = threadIdx.x;

    __shared__ float2 lam[NST], w00[NST], w01[NST], w10[NST];
    __shared__ float  w11[NST];
    extern __shared__ float2 x[];   // SPAD float2

    if (tid < NST) {
        int n = tid;
        lam[n] = make_float2(Lr[n], Li[n]);
        float2 P  = make_float2(Pr[n], Pi[n]);
        float2 Bv = make_float2(Br[n], Bi[n]);
        float2 Cc = make_float2(Cr[h * NST + n], -Ci[h * NST + n]);
        w00[n] = cmul(Cc, Bv);
        w01[n] = cmul(Cc, P);
        float2 Qc = make_float2(P.x, -P.y);
        w10[n] = cmul(Qc, Bv);
        w11[n] = P.x * P.x + P.y * P.y;
    }
    __syncthreads();

    const float dt = expf(logdt[h]);
    const float g0 = 2.0f / dt;

    // ---- at_roots into x[0..2047] (natural order), pairing l with 2048-l ----
    for (int l = tid; l < 1024; l += blockDim.x) {
        float ss, cc;
        sincospif((float)l * (1.0f / 1024.0f), &ss, &cc);
        float2 om = make_float2(cc, -ss);
        float2 den = make_float2(1.f + om.x, om.y);
        float2 num = make_float2(1.f - om.x, -om.y);
        float idl  = __fdividef(1.f, den.x * den.x + den.y * den.y);
        float2 c2  = make_float2(2.f * den.x * idl, -2.f * den.y * idl);
        float2 gf  = cmul(num, make_float2(den.x, -den.y));
        float2 g   = make_float2(g0 * gf.x * idl, g0 * gf.y * idl);

        float2 a00 = {0.f, 0.f}, a01 = {0.f, 0.f}, a10 = {0.f, 0.f}, a11 = {0.f, 0.f};
        float2 b00 = {0.f, 0.f}, b01 = {0.f, 0.f}, b10 = {0.f, 0.f}, b11 = {0.f, 0.f};
#pragma unroll 4
        for (int n = 0; n < NST; n++) {
            float dx  = g.x - lam[n].x;
            float dy  = g.y - lam[n].y;
            float inv = __fdividef(1.f, dx * dx + dy * dy);
            float2 r  = make_float2(dx * inv, -dy * inv);     // 1/(g - lam_n)
            a00 = cadd(a00, cmul(w00[n], r));
            a01 = cadd(a01, cmul(w01[n], r));
            a10 = cadd(a10, cmul(w10[n], r));
            a11.x = fmaf(w11[n], r.x, a11.x);
            a11.y = fmaf(w11[n], r.y, a11.y);
            int m = NST - 1 - n;
            float2 rc = make_float2(r.x, -r.y);
            b00 = cadd(b00, cmul(w00[m], rc));
            b01 = cadd(b01, cmul(w01[m], rc));
            b10 = cadd(b10, cmul(w10[m], rc));
            b11.x = fmaf(w11[m], rc.x, b11.x);
            b11.y = fmaf(w11[m], rc.y, b11.y);
        }
        {   // A[l]
            float2 onep = make_float2(1.f + a11.x, a11.y);
            float  ip   = __fdividef(1.f, onep.x * onep.x + onep.y * onep.y);
            float2 invd = make_float2(onep.x * ip, -onep.y * ip);
            float2 t2   = cmul(cmul(a01, a10), invd);
            x[SIDX(l)]  = cmul(c2, csub(a00, t2));
        }
        if (l != 0) {   // A[2048-l], c2' = conj(c2)
            float2 c2c  = make_float2(c2.x, -c2.y);
            float2 onep = make_float2(1.f + b11.x, b11.y);
            float  ip   = __fdividef(1.f, onep.x * onep.x + onep.y * onep.y);
            float2 invd = make_float2(onep.x * ip, -onep.y * ip);
            float2 t2   = cmul(cmul(b01, b10), invd);
            x[SIDX(2048 - l)] = cmul(c2c, csub(b00, t2));
        }
    }
    if (tid == 0) {
        // l = 1024: omega = -1, analytic limit: at -> dt * sum(w00) / 2
        float2 s = make_float2(0.f, 0.f);
        for (int n = 0; n < NST; n++) s = cadd(s, w00[n]);
        x[SIDX(1024)] = make_float2(0.5f * dt * s.x, 0.5f * dt * s.y);
    }
    __syncthreads();

    // ---- inverse FFT 2048 (radix-2 DIF, conj tw): natural -> bit-reversed ----
    {
        int step = 2;
        for (int mh = 1024; mh >= 1; mh >>= 1, step <<= 1) {
            for (int t = tid; t < 1024; t += blockDim.x) {
                int k  = t & (mh - 1);
                int i0 = 2 * t - k, i1 = i0 + mh;
                float2 a = x[SIDX(i0)], b = x[SIDX(i1)];
                x[SIDX(i0)] = cadd(a, b);
                x[SIDX(i1)] = cmul(csub(a, b), tw4096c(k * step));
            }
            __syncthreads();
        }
    }
    // bit-reverse (11-bit) to natural order
    for (int i = tid; i < 2048; i += blockDim.x) {
        int r = __brev(i) >> 21;
        if (r > i) { float2 t = x[SIDX(i)]; x[SIDX(i)] = x[SIDX(r)]; x[SIDX(r)] = t; }
    }
    __syncthreads();
    const float sc = 1.0f / 2048.0f;
    for (int i = tid; i < 2048; i += blockDim.x) {
        float2 t = x[SIDX(i)];
        x[SIDX(i)] = make_float2(t.x * sc, 0.f);
    }
    for (int i = 2048 + tid; i < NFFT; i += blockDim.x) x[SIDX(i)] = make_float2(0.f, 0.f);
    __syncthreads();

    // ---- forward FFT 4096: 3 register-radix-16 passes ----
    float2 v[16];
#pragma unroll
    for (int j = 0; j < 16; j++) v[j] = x[SIDX(tid + 256 * j)];
    fwd16(v, tw4096(tid));
#pragma unroll
    for (int j = 0; j < 16; j++) x[SIDX(tid + 256 * j)] = v[j];
    __syncthreads();

    const int base2 = ((tid >> 4) << 8) + (tid & 15);
#pragma unroll
    for (int j = 0; j < 16; j++) v[j] = x[SIDX(base2 + 16 * j)];
    fwd16(v, tw4096((tid & 15) << 4));
#pragma unroll
    for (int j = 0; j < 16; j++) x[SIDX(base2 + 16 * j)] = v[j];
    __syncthreads();

#pragma unroll
    for (int j = 0; j < 16; j++) v[j] = x[SIDX(16 * tid + j)];
    fwd16(v, make_float2(1.f, 0.f));

    // store in conv-friendly layout: d_Kf[h][j*256 + tid] (coalesced)
    float2* kf = d_Kf + (size_t)h * NFFT;
#pragma unroll
    for (int j = 0; j < 16; j++) kf[j * 256 + tid] = v[j];
}

// ---------------------------------------------------------------------------
// Kernel C: batch-paired FFT convolution + skip.
// CTA = (h, batch-pair). z = u[b0] + i*u[b1], SAME channel h => pointwise
// multiply by one real-kernel spectrum, NO Hermitian split / exchange:
// IFFT(Z * K^) = conv(u_b0, K) + i*conv(u_b1, K) since K is real.
// ---------------------------------------------------------------------------
__global__ void __launch_bounds__(256, 2) kernel_conv(
        const float* __restrict__ u, const float* __restrict__ D,
        float* __restrict__ y) {
    const int h  = blockIdx.x;
    const int bp = blockIdx.y;                 // batch pair: (2bp, 2bp+1)
    const int t  = threadIdx.x;
    extern __shared__ float2 x[];   // SPAD float2

    const float* ua = u + (size_t)(2 * bp) * LSEQ * HCH + h;
    const float* ub = u + (size_t)(2 * bp + 1) * LSEQ * HCH + h;
    float2 v[16];
#pragma unroll
    for (int j = 0; j < 8; j++) {
        int l = t + 256 * j;
        v[j] = make_float2(ua[(size_t)l * HCH], ub[(size_t)l * HCH]);
    }
#pragma unroll
    for (int j = 8; j < 16; j++) v[j] = make_float2(0.f, 0.f);

    // ---- forward 4096 ----
    const float2 w1 = tw4096(t);
    fwd16(v, w1);
#pragma unroll
    for (int j = 0; j < 16; j++) x[SIDX(t + 256 * j)] = v[j];
    __syncthreads();

    const int base2 = ((t >> 4) << 8) + (t & 15);
    const float2 wp2 = tw4096((t & 15) << 4);
#pragma unroll
    for (int j = 0; j < 16; j++) v[j] = x[SIDX(base2 + 16 * j)];
    fwd16(v, wp2);
#pragma unroll
    for (int j = 0; j < 16; j++) x[SIDX(base2 + 16 * j)] = v[j];
    __syncthreads();

#pragma unroll
    for (int j = 0; j < 16; j++) v[j] = x[SIDX(16 * t + j)];
    fwd16(v, make_float2(1.f, 0.f));

    // pointwise multiply in registers (matched bit-reversed layouts)
    const float2* kf = d_Kf + (size_t)h * NFFT;
#pragma unroll
    for (int j = 0; j < 16; j++) v[j] = cmul(v[j], kf[j * 256 + t]);
    __syncthreads();                            // pass-3 readers done before overwrite

    // ---- inverse 4096 ----
    inv16(v, make_float2(1.f, 0.f));
#pragma unroll
    for (int j = 0; j < 16; j++) x[SIDX(16 * t + j)] = v[j];
    __syncthreads();

#pragma unroll
    for (int j = 0; j < 16; j++) v[j] = x[SIDX(base2 + 16 * j)];
    inv16(v, wp2);
#pragma unroll
    for (int j = 0; j < 16; j++) x[SIDX(base2 + 16 * j)] = v[j];
    __syncthreads();

#pragma unroll
    for (int j = 0; j < 16; j++) v[j] = x[SIDX(t + 256 * j)];
    inv16(v, w1);
    // v[j] = y_b0(l) + i*y_b1(l) at natural time l = t + 256*j (times NFFT)

    const float Dh  = D[h];
    const float inv = 1.0f / (float)NFFT;
    float* ya = y + (size_t)(2 * bp) * LSEQ * HCH + h;
    float* yb = y + (size_t)(2 * bp + 1) * LSEQ * HCH + h;
#pragma unroll
    for (int j = 0; j < 8; j++) {
        int l = t + 256 * j;
        float uua = ua[(size_t)l * HCH];
        float uub = ub[(size_t)l * HCH];
        ya[(size_t)l * HCH] = fmaf(v[j].x, inv, uua * Dh);
        yb[(size_t)l * HCH] = fmaf(v[j].y, inv, uub * Dh);
    }
}

// ---------------------------------------------------------------------------
extern "C" void kernel_launch(void* const* d_in, const int* in_sizes, int n_in,
                              void* d_out, int out_size) {
    const float* u   = (const float*)d_in[0];
    const float* Lr  = (const float*)d_in[1];
    const float* Li  = (const float*)d_in[2];
    const float* Pr  = (const float*)d_in[3];
    const float* Pi  = (const float*)d_in[4];
    const float* Br  = (const float*)d_in[5];
    const float* Bi  = (const float*)d_in[6];
    const float* Cr  = (const float*)d_in[7];
    const float* Ci  = (const float*)d_in[8];
    const float* ldt = (const float*)d_in[9];
    const float* D   = (const float*)d_in[10];
    float* y = (float*)d_out;

    const size_t smem = (size_t)SPAD * sizeof(float2);   // 34816 B

    kernel_spec<<<HCH, 256, smem>>>(Lr, Li, Pr, Pi, Br, Bi, Cr, Ci, ldt);
    kernel_conv<<<dim3(HCH, BS / 2), 256, smem>>>(u, D, y);
}

// round 10
// speedup vs baseline: 1.2105x; 1.1005x over previous
#include <cuda_runtime.h>
#include <math.h>

#define HCH  512
#define NST  64
#define BS   8
#define LSEQ 2048
#define NFFT 4096
#define SIDX(i) ((i) + ((i) >> 4))
#define SPAD (NFFT + (NFFT >> 4))   // 4352 float2 = 34816 B

// per-channel spectrum, layout [h][j*256 + t] holding bit-rev position p=16t+j
__device__ float2 d_Kf[(size_t)HCH * NFFT];

// W16^m = exp(-2*pi*i*m/16), m=0..7
__constant__ float2 C16[8] = {
    { 1.0f,           0.0f},
    { 0.92387953251f, -0.38268343236f},
    { 0.70710678119f, -0.70710678119f},
    { 0.38268343236f, -0.92387953251f},
    { 0.0f,          -1.0f},
    {-0.38268343236f, -0.92387953251f},
    {-0.70710678119f, -0.70710678119f},
    {-0.92387953251f, -0.38268343236f},
};

__device__ __forceinline__ float2 cmul(float2 a, float2 b) {
    return make_float2(fmaf(a.x, b.x, -a.y * b.y), fmaf(a.x, b.y, a.y * b.x));
}
__device__ __forceinline__ float2 cmulj(float2 a, float2 b) {   // a * conj(b)
    return make_float2(fmaf(a.x, b.x, a.y * b.y), fmaf(a.y, b.x, -a.x * b.y));
}
__device__ __forceinline__ float2 cadd(float2 a, float2 b) { return make_float2(a.x + b.x, a.y + b.y); }
__device__ __forceinline__ float2 csub(float2 a, float2 b) { return make_float2(a.x - b.x, a.y - b.y); }

// W4096^j = exp(-2*pi*i*j/4096), exact-argument via sincospif
__device__ __forceinline__ float2 tw4096(int j) {
    float s, c;
    sincospif((float)j * (1.0f / 2048.0f), &s, &c);
    return make_float2(c, -s);
}
__device__ __forceinline__ float2 tw4096c(int j) {
    float s, c;
    sincospif((float)j * (1.0f / 2048.0f), &s, &c);
    return make_float2(c, s);
}

// ---------------------------------------------------------------------------
// 16-point register FFT blocks (3 passes = full radix-2 DIF; position p ends
// holding frequency brev12(p)).
// ---------------------------------------------------------------------------
__device__ __forceinline__ void fwd16(float2* v, float2 w1) {
    float2 w2 = cmul(w1, w1), w4 = cmul(w2, w2), w8 = cmul(w4, w4);
#pragma unroll
    for (int j = 0; j < 8; j++) {
        float2 tw = cmul(w1, C16[j]);
        float2 a = v[j], bb = v[j + 8];
        v[j] = cadd(a, bb);
        v[j + 8] = cmul(csub(a, bb), tw);
    }
#pragma unroll
    for (int g = 0; g < 16; g += 8)
#pragma unroll
        for (int j = 0; j < 4; j++) {
            float2 tw = cmul(w2, C16[2 * j]);
            float2 a = v[g + j], bb = v[g + j + 4];
            v[g + j] = cadd(a, bb);
            v[g + j + 4] = cmul(csub(a, bb), tw);
        }
#pragma unroll
    for (int g = 0; g < 16; g += 4)
#pragma unroll
        for (int j = 0; j < 2; j++) {
            float2 tw = cmul(w4, C16[4 * j]);
            float2 a = v[g + j], bb = v[g + j + 2];
            v[g + j] = cadd(a, bb);
            v[g + j + 2] = cmul(csub(a, bb), tw);
        }
#pragma unroll
    for (int g = 0; g < 16; g += 2) {
        float2 a = v[g], bb = v[g + 1];
        v[g] = cadd(a, bb);
        v[g + 1] = cmul(csub(a, bb), w8);
    }
}

__device__ __forceinline__ void inv16(float2* v, float2 w1) {
    float2 c1 = make_float2(w1.x, -w1.y);
    float2 c2 = cmul(c1, c1), c4 = cmul(c2, c2), c8 = cmul(c4, c4);
#pragma unroll
    for (int g = 0; g < 16; g += 2) {
        float2 tb = cmul(v[g + 1], c8);
        float2 a = v[g];
        v[g] = cadd(a, tb);
        v[g + 1] = csub(a, tb);
    }
#pragma unroll
    for (int g = 0; g < 16; g += 4)
#pragma unroll
        for (int j = 0; j < 2; j++) {
            float2 tw = cmulj(c4, C16[4 * j]);
            float2 tb = cmul(v[g + j + 2], tw);
            float2 a = v[g + j];
            v[g + j] = cadd(a, tb);
            v[g + j + 2] = csub(a, tb);
        }
#pragma unroll
    for (int g = 0; g < 16; g += 8)
#pragma unroll
        for (int j = 0; j < 4; j++) {
            float2 tw = cmulj(c2, C16[2 * j]);
            float2 tb = cmul(v[g + j + 4], tw);
            float2 a = v[g + j];
            v[g + j] = cadd(a, tb);
            v[g + j + 4] = csub(a, tb);
        }
#pragma unroll
    for (int j = 0; j < 8; j++) {
        float2 tw = cmulj(c1, C16[j]);
        float2 tb = cmul(v[j + 8], tw);
        float2 a = v[j];
        v[j] = cadd(a, tb);
        v[j + 8] = csub(a, tb);
    }
}

// One full 4096 FFT-conv-IFFT on v[16] through smem x.
// Sync analysis: pass-3 loads and inv-pass-1 stores use identical per-thread
// address sets {16t+j}, so no barrier is needed between them; likewise between
// the trailing inv-pass-3 load {t+256j} and a following call's pass-1 store.
__device__ __forceinline__ void fft_conv_4096(
        float2* v, float2* x, int t, int base2,
        float2 w1, float2 wp2, const float2* __restrict__ kf) {
    fwd16(v, w1);
#pragma unroll
    for (int j = 0; j < 16; j++) x[SIDX(t + 256 * j)] = v[j];
    __syncthreads();
#pragma unroll
    for (int j = 0; j < 16; j++) v[j] = x[SIDX(base2 + 16 * j)];
    fwd16(v, wp2);
#pragma unroll
    for (int j = 0; j < 16; j++) x[SIDX(base2 + 16 * j)] = v[j];
    __syncthreads();
#pragma unroll
    for (int j = 0; j < 16; j++) v[j] = x[SIDX(16 * t + j)];
    fwd16(v, make_float2(1.f, 0.f));
    // pointwise multiply in registers (matched bit-reversed layouts)
#pragma unroll
    for (int j = 0; j < 16; j++) v[j] = cmul(v[j], kf[j * 256 + t]);
    inv16(v, make_float2(1.f, 0.f));
#pragma unroll
    for (int j = 0; j < 16; j++) x[SIDX(16 * t + j)] = v[j];
    __syncthreads();
#pragma unroll
    for (int j = 0; j < 16; j++) v[j] = x[SIDX(base2 + 16 * j)];
    inv16(v, wp2);
#pragma unroll
    for (int j = 0; j < 16; j++) x[SIDX(base2 + 16 * j)] = v[j];
    __syncthreads();
#pragma unroll
    for (int j = 0; j < 16; j++) v[j] = x[SIDX(t + 256 * j)];
    inv16(v, w1);
}

// ---------------------------------------------------------------------------
// Kernel B: per-channel spectral kernel build (R5-exact configuration).
// ---------------------------------------------------------------------------
__global__ void __launch_bounds__(256) kernel_spec(
        const float* __restrict__ Lr, const float* __restrict__ Li,
        const float* __restrict__ Pr, const float* __restrict__ Pi,
        const float* __restrict__ Br, const float* __restrict__ Bi,
        const float* __restrict__ Cr, const float* __restrict__ Ci,
        const float* __restrict__ logdt) {
    const int h   = blockIdx.x;
    const int tid = threadIdx.x;

    __shared__ float2 lam[NST], w00[NST], w01[NST], w10[NST];
    __shared__ float  w11[NST];
    extern __shared__ float2 x[];   // SPAD float2

    if (tid < NST) {
        int n = tid;
        lam[n] = make_float2(Lr[n], Li[n]);
        float2 P  = make_float2(Pr[n], Pi[n]);
        float2 Bv = make_float2(Br[n], Bi[n]);
        float2 Cc = make_float2(Cr[h * NST + n], -Ci[h * NST + n]);
        w00[n] = cmul(Cc, Bv);
        w01[n] = cmul(Cc, P);
        float2 Qc = make_float2(P.x, -P.y);
        w10[n] = cmul(Qc, Bv);
        w11[n] = P.x * P.x + P.y * P.y;
    }
    __syncthreads();

    const float dt = expf(logdt[h]);
    const float g0 = 2.0f / dt;

    // ---- at_roots into x[0..2047] (natural order), pairing l with 2048-l ----
    for (int l = tid; l < 1024; l += blockDim.x) {
        float ss, cc;
        sincospif((float)l * (1.0f / 1024.0f), &ss, &cc);
        float2 om = make_float2(cc, -ss);
        float2 den = make_float2(1.f + om.x, om.y);
        float2 num = make_float2(1.f - om.x, -om.y);
        float idl  = __fdividef(1.f, den.x * den.x + den.y * den.y);
        float2 c2  = make_float2(2.f * den.x * idl, -2.f * den.y * idl);
        float2 gf  = cmul(num, make_float2(den.x, -den.y));
        float2 g   = make_float2(g0 * gf.x * idl, g0 * gf.y * idl);

        float2 a00 = {0.f, 0.f}, a01 = {0.f, 0.f}, a10 = {0.f, 0.f}, a11 = {0.f, 0.f};
        float2 b00 = {0.f, 0.f}, b01 = {0.f, 0.f}, b10 = {0.f, 0.f}, b11 = {0.f, 0.f};
#pragma unroll 4
        for (int n = 0; n < NST; n++) {
            float dx  = g.x - lam[n].x;
            float dy  = g.y - lam[n].y;
            float inv = __fdividef(1.f, dx * dx + dy * dy);
            float2 r  = make_float2(dx * inv, -dy * inv);     // 1/(g - lam_n)
            a00 = cadd(a00, cmul(w00[n], r));
            a01 = cadd(a01, cmul(w01[n], r));
            a10 = cadd(a10, cmul(w10[n], r));
            a11.x = fmaf(w11[n], r.x, a11.x);
            a11.y = fmaf(w11[n], r.y, a11.y);
            int m = NST - 1 - n;
            float2 rc = make_float2(r.x, -r.y);
            b00 = cadd(b00, cmul(w00[m], rc));
            b01 = cadd(b01, cmul(w01[m], rc));
            b10 = cadd(b10, cmul(w10[m], rc));
            b11.x = fmaf(w11[m], rc.x, b11.x);
            b11.y = fmaf(w11[m], rc.y, b11.y);
        }
        {   // A[l]
            float2 onep = make_float2(1.f + a11.x, a11.y);
            float  ip   = __fdividef(1.f, onep.x * onep.x + onep.y * onep.y);
            float2 invd = make_float2(onep.x * ip, -onep.y * ip);
            float2 t2   = cmul(cmul(a01, a10), invd);
            x[SIDX(l)]  = cmul(c2, csub(a00, t2));
        }
        if (l != 0) {   // A[2048-l], c2' = conj(c2)
            float2 c2c  = make_float2(c2.x, -c2.y);
            float2 onep = make_float2(1.f + b11.x, b11.y);
            float  ip   = __fdividef(1.f, onep.x * onep.x + onep.y * onep.y);
            float2 invd = make_float2(onep.x * ip, -onep.y * ip);
            float2 t2   = cmul(cmul(b01, b10), invd);
            x[SIDX(2048 - l)] = cmul(c2c, csub(b00, t2));
        }
    }
    if (tid == 0) {
        // l = 1024: omega = -1, analytic limit: at -> dt * sum(w00) / 2
        float2 s = make_float2(0.f, 0.f);
        for (int n = 0; n < NST; n++) s = cadd(s, w00[n]);
        x[SIDX(1024)] = make_float2(0.5f * dt * s.x, 0.5f * dt * s.y);
    }
    __syncthreads();

    // ---- inverse FFT 2048 (radix-2 DIF, conj tw): natural -> bit-reversed ----
    {
        int step = 2;
        for (int mh = 1024; mh >= 1; mh >>= 1, step <<= 1) {
            for (int t = tid; t < 1024; t += blockDim.x) {
                int k  = t & (mh - 1);
                int i0 = 2 * t - k, i1 = i0 + mh;
                float2 a = x[SIDX(i0)], b = x[SIDX(i1)];
                x[SIDX(i0)] = cadd(a, b);
                x[SIDX(i1)] = cmul(csub(a, b), tw4096c(k * step));
            }
            __syncthreads();
        }
    }
    // bit-reverse (11-bit) to natural order
    for (int i = tid; i < 2048; i += blockDim.x) {
        int r = __brev(i) >> 21;
        if (r > i) { float2 t = x[SIDX(i)]; x[SIDX(i)] = x[SIDX(r)]; x[SIDX(r)] = t; }
    }
    __syncthreads();
    const float sc = 1.0f / 2048.0f;
    for (int i = tid; i < 2048; i += blockDim.x) {
        float2 t = x[SIDX(i)];
        x[SIDX(i)] = make_float2(t.x * sc, 0.f);
    }
    for (int i = 2048 + tid; i < NFFT; i += blockDim.x) x[SIDX(i)] = make_float2(0.f, 0.f);
    __syncthreads();

    // ---- forward FFT 4096: 3 register-radix-16 passes ----
    float2 v[16];
#pragma unroll
    for (int j = 0; j < 16; j++) v[j] = x[SIDX(tid + 256 * j)];
    fwd16(v, tw4096(tid));
#pragma unroll
    for (int j = 0; j < 16; j++) x[SIDX(tid + 256 * j)] = v[j];
    __syncthreads();

    const int base2 = ((tid >> 4) << 8) + (tid & 15);
#pragma unroll
    for (int j = 0; j < 16; j++) v[j] = x[SIDX(base2 + 16 * j)];
    fwd16(v, tw4096((tid & 15) << 4));
#pragma unroll
    for (int j = 0; j < 16; j++) x[SIDX(base2 + 16 * j)] = v[j];
    __syncthreads();

#pragma unroll
    for (int j = 0; j < 16; j++) v[j] = x[SIDX(16 * tid + j)];
    fwd16(v, make_float2(1.f, 0.f));

    // store in conv-friendly layout: d_Kf[h][j*256 + tid] (coalesced)
    float2* kf = d_Kf + (size_t)h * NFFT;
#pragma unroll
    for (int j = 0; j < 16; j++) kf[j * 256 + tid] = v[j];
}

// ---------------------------------------------------------------------------
// Kernel C: channel-pair x batch-pair FFT convolution + skip.
// CTA = (hp, bp): channels (2hp, 2hp+1), batches (2bp, 2bp+1).
// Each float2 load of u[b][l][2hp:2hp+2] feeds two batch-paired complex
// sequences (K real => IFFT(Z*K^) = conv_b0 + i*conv_b1 exactly).
// Two sequential FFTs; z1 and y0 parked in registers. Vectorized float2
// u loads / y stores, no Hermitian exchange, Kf read once per channel.
// ---------------------------------------------------------------------------
__global__ void __launch_bounds__(256, 2) kernel_conv(
        const float* __restrict__ u, const float* __restrict__ D,
        float* __restrict__ y) {
    const int hp = blockIdx.x;                 // channel pair (2hp, 2hp+1)
    const int bp = blockIdx.y;                 // batch pair (2bp, 2bp+1)
    const int t  = threadIdx.x;
    extern __shared__ float2 x[];   // SPAD float2

    const float2* ua2 = (const float2*)(u + (size_t)(2 * bp) * LSEQ * HCH) + hp;
    const float2* ub2 = (const float2*)(u + (size_t)(2 * bp + 1) * LSEQ * HCH) + hp;

    float2 v[16], z1[8], y0[8];
#pragma unroll
    for (int j = 0; j < 8; j++) {
        size_t idx = (size_t)(t + 256 * j) * (HCH / 2);
        float2 la = ua2[idx];                  // u[b0][l][2hp], u[b0][l][2hp+1]
        float2 lb = ub2[idx];                  // u[b1][l][2hp], u[b1][l][2hp+1]
        v[j]  = make_float2(la.x, lb.x);       // channel 2hp:   b0 + i*b1
        z1[j] = make_float2(la.y, lb.y);       // channel 2hp+1: b0 + i*b1
    }
#pragma unroll
    for (int j = 8; j < 16; j++) v[j] = make_float2(0.f, 0.f);

    const float2 w1  = tw4096(t);
    const float2 wp2 = tw4096((t & 15) << 4);
    const int base2  = ((t >> 4) << 8) + (t & 15);

    // ---- FFT-conv #0: channel 2hp ----
    fft_conv_4096(v, x, t, base2, w1, wp2, d_Kf + (size_t)(2 * hp) * NFFT);
#pragma unroll
    for (int j = 0; j < 8; j++) y0[j] = v[j];

    // ---- FFT-conv #1: channel 2hp+1 ----
#pragma unroll
    for (int j = 0; j < 8; j++) v[j] = z1[j];
#pragma unroll
    for (int j = 8; j < 16; j++) v[j] = make_float2(0.f, 0.f);
    fft_conv_4096(v, x, t, base2, w1, wp2, d_Kf + (size_t)(2 * hp + 1) * NFFT);

    // ---- epilogue: combine channels back into float2 stores ----
    const float D0  = D[2 * hp];
    const float D1  = D[2 * hp + 1];
    const float inv = 1.0f / (float)NFFT;
    float2* ya2 = (float2*)(y + (size_t)(2 * bp) * LSEQ * HCH) + hp;
    float2* yb2 = (float2*)(y + (size_t)(2 * bp + 1) * LSEQ * HCH) + hp;
#pragma unroll
    for (int j = 0; j < 8; j++) {
        size_t idx = (size_t)(t + 256 * j) * (HCH / 2);
        float2 la = ua2[idx];
        float2 lb = ub2[idx];
        float2 oa, ob;
        oa.x = fmaf(y0[j].x, inv, la.x * D0);  // y[b0][l][2hp]
        oa.y = fmaf(v[j].x,  inv, la.y * D1);  // y[b0][l][2hp+1]
        ob.x = fmaf(y0[j].y, inv, lb.x * D0);  // y[b1][l][2hp]
        ob.y = fmaf(v[j].y,  inv, lb.y * D1);  // y[b1][l][2hp+1]
        ya2[idx] = oa;
        yb2[idx] = ob;
    }
}

// ---------------------------------------------------------------------------
extern "C" void kernel_launch(void* const* d_in, const int* in_sizes, int n_in,
                              void* d_out, int out_size) {
    const float* u   = (const float*)d_in[0];
    const float* Lr  = (const float*)d_in[1];
    const float* Li  = (const float*)d_in[2];
    const float* Pr  = (const float*)d_in[3];
    const float* Pi  = (const float*)d_in[4];
    const float* Br  = (const float*)d_in[5];
    const float* Bi  = (const float*)d_in[6];
    const float* Cr  = (const float*)d_in[7];
    const float* Ci  = (const float*)d_in[8];
    const float* ldt = (const float*)d_in[9];
    const float* D   = (const float*)d_in[10];
    float* y = (float*)d_out;

    const size_t smem = (size_t)SPAD * sizeof(float2);   // 34816 B

    kernel_spec<<<HCH, 256, smem>>>(Lr, Li, Pr, Pi, Br, Bi, Cr, Ci, ldt);
    kernel_conv<<<dim3(HCH / 2, BS / 2), 256, smem>>>(u, D, y);
}

// round 11
// speedup vs baseline: 1.2367x; 1.0217x over previous
#include <cuda_runtime.h>
#include <math.h>

#define HCH  512
#define NST  64
#define BS   8
#define LSEQ 2048
#define NFFT 4096
#define SIDX(i) ((i) + ((i) >> 4))
#define SPAD (NFFT + (NFFT >> 4))   // 4352 float2 = 34816 B

// per-channel spectrum, layout [h][j*256 + t] holding bit-rev position p=16t+j
__device__ float2 d_Kf[(size_t)HCH * NFFT];

// W16^m = exp(-2*pi*i*m/16), m=0..7
__constant__ float2 C16[8] = {
    { 1.0f,           0.0f},
    { 0.92387953251f, -0.38268343236f},
    { 0.70710678119f, -0.70710678119f},
    { 0.38268343236f, -0.92387953251f},
    { 0.0f,          -1.0f},
    {-0.38268343236f, -0.92387953251f},
    {-0.70710678119f, -0.70710678119f},
    {-0.92387953251f, -0.38268343236f},
};

typedef unsigned long long u64c;

// ---- packed f32x2 helpers (sm_100a) ----
__device__ __forceinline__ u64c pk2(float lo, float hi) {
    u64c r; asm("mov.b64 %0, {%1, %2};" : "=l"(r) : "f"(lo), "f"(hi)); return r;
}
__device__ __forceinline__ float2 unpk2(u64c v) {
    float lo, hi; asm("mov.b64 {%0, %1}, %2;" : "=f"(lo), "=f"(hi) : "l"(v));
    return make_float2(lo, hi);
}
// d = a*b + c, elementwise on packed f32x2
__device__ __forceinline__ u64c ffma2_(u64c a, u64c b, u64c c) {
    u64c r; asm("fma.rn.f32x2 %0, %1, %2, %3;" : "=l"(r) : "l"(a), "l"(b), "l"(c));
    return r;
}

__device__ __forceinline__ float2 cmul(float2 a, float2 b) {
    return make_float2(fmaf(a.x, b.x, -a.y * b.y), fmaf(a.x, b.y, a.y * b.x));
}
__device__ __forceinline__ float2 cmulj(float2 a, float2 b) {   // a * conj(b)
    return make_float2(fmaf(a.x, b.x, a.y * b.y), fmaf(a.y, b.x, -a.x * b.y));
}
__device__ __forceinline__ float2 cadd(float2 a, float2 b) { return make_float2(a.x + b.x, a.y + b.y); }
__device__ __forceinline__ float2 csub(float2 a, float2 b) { return make_float2(a.x - b.x, a.y - b.y); }

// W4096^j = exp(-2*pi*i*j/4096), exact-argument via sincospif
__device__ __forceinline__ float2 tw4096(int j) {
    float s, c;
    sincospif((float)j * (1.0f / 2048.0f), &s, &c);
    return make_float2(c, -s);
}
__device__ __forceinline__ float2 tw4096c(int j) {
    float s, c;
    sincospif((float)j * (1.0f / 2048.0f), &s, &c);
    return make_float2(c, s);
}

// ---------------------------------------------------------------------------
// 16-point register FFT blocks (3 passes = full radix-2 DIF; position p ends
// holding frequency brev12(p)).
// ---------------------------------------------------------------------------
__device__ __forceinline__ void fwd16(float2* v, float2 w1) {
    float2 w2 = cmul(w1, w1), w4 = cmul(w2, w2), w8 = cmul(w4, w4);
#pragma unroll
    for (int j = 0; j < 8; j++) {
        float2 tw = cmul(w1, C16[j]);
        float2 a = v[j], bb = v[j + 8];
        v[j] = cadd(a, bb);
        v[j + 8] = cmul(csub(a, bb), tw);
    }
#pragma unroll
    for (int g = 0; g < 16; g += 8)
#pragma unroll
        for (int j = 0; j < 4; j++) {
            float2 tw = cmul(w2, C16[2 * j]);
            float2 a = v[g + j], bb = v[g + j + 4];
            v[g + j] = cadd(a, bb);
            v[g + j + 4] = cmul(csub(a, bb), tw);
        }
#pragma unroll
    for (int g = 0; g < 16; g += 4)
#pragma unroll
        for (int j = 0; j < 2; j++) {
            float2 tw = cmul(w4, C16[4 * j]);
            float2 a = v[g + j], bb = v[g + j + 2];
            v[g + j] = cadd(a, bb);
            v[g + j + 2] = cmul(csub(a, bb), tw);
        }
#pragma unroll
    for (int g = 0; g < 16; g += 2) {
        float2 a = v[g], bb = v[g + 1];
        v[g] = cadd(a, bb);
        v[g + 1] = cmul(csub(a, bb), w8);
    }
}

__device__ __forceinline__ void inv16(float2* v, float2 w1) {
    float2 c1 = make_float2(w1.x, -w1.y);
    float2 c2 = cmul(c1, c1), c4 = cmul(c2, c2), c8 = cmul(c4, c4);
#pragma unroll
    for (int g = 0; g < 16; g += 2) {
        float2 tb = cmul(v[g + 1], c8);
        float2 a = v[g];
        v[g] = cadd(a, tb);
        v[g + 1] = csub(a, tb);
    }
#pragma unroll
    for (int g = 0; g < 16; g += 4)
#pragma unroll
        for (int j = 0; j < 2; j++) {
            float2 tw = cmulj(c4, C16[4 * j]);
            float2 tb = cmul(v[g + j + 2], tw);
            float2 a = v[g + j];
            v[g + j] = cadd(a, tb);
            v[g + j + 2] = csub(a, tb);
        }
#pragma unroll
    for (int g = 0; g < 16; g += 8)
#pragma unroll
        for (int j = 0; j < 4; j++) {
            float2 tw = cmulj(c2, C16[2 * j]);
            float2 tb = cmul(v[g + j + 4], tw);
            float2 a = v[g + j];
            v[g + j] = cadd(a, tb);
            v[g + j + 4] = csub(a, tb);
        }
#pragma unroll
    for (int j = 0; j < 8; j++) {
        float2 tw = cmulj(c1, C16[j]);
        float2 tb = cmul(v[j + 8], tw);
        float2 a = v[j];
        v[j] = cadd(a, tb);
        v[j + 8] = csub(a, tb);
    }
}

// One full 4096 FFT-conv-IFFT on v[16] through smem x.
__device__ __forceinline__ void fft_conv_4096(
        float2* v, float2* x, int t, int base2,
        float2 w1, float2 wp2, const float2* __restrict__ kf) {
    fwd16(v, w1);
#pragma unroll
    for (int j = 0; j < 16; j++) x[SIDX(t + 256 * j)] = v[j];
    __syncthreads();
#pragma unroll
    for (int j = 0; j < 16; j++) v[j] = x[SIDX(base2 + 16 * j)];
    fwd16(v, wp2);
#pragma unroll
    for (int j = 0; j < 16; j++) x[SIDX(base2 + 16 * j)] = v[j];
    __syncthreads();
#pragma unroll
    for (int j = 0; j < 16; j++) v[j] = x[SIDX(16 * t + j)];
    fwd16(v, make_float2(1.f, 0.f));
#pragma unroll
    for (int j = 0; j < 16; j++) v[j] = cmul(v[j], kf[j * 256 + t]);
    inv16(v, make_float2(1.f, 0.f));
#pragma unroll
    for (int j = 0; j < 16; j++) x[SIDX(16 * t + j)] = v[j];
    __syncthreads();
#pragma unroll
    for (int j = 0; j < 16; j++) v[j] = x[SIDX(base2 + 16 * j)];
    inv16(v, wp2);
#pragma unroll
    for (int j = 0; j < 16; j++) x[SIDX(base2 + 16 * j)] = v[j];
    __syncthreads();
#pragma unroll
    for (int j = 0; j < 16; j++) v[j] = x[SIDX(t + 256 * j)];
    inv16(v, w1);
}

// ---------------------------------------------------------------------------
// Kernel B: per-channel spectral kernel build.
// Cauchy loop SIMD-packed across the (l, 2048-l) conjugate-pair lanes using
// fma.rn.f32x2: lane 0 = a-side (freq l), lane 1 = b-side (freq 2048-l).
// ---------------------------------------------------------------------------
__global__ void __launch_bounds__(256) kernel_spec(
        const float* __restrict__ Lr, const float* __restrict__ Li,
        const float* __restrict__ Pr, const float* __restrict__ Pi,
        const float* __restrict__ Br, const float* __restrict__ Bi,
        const float* __restrict__ Cr, const float* __restrict__ Ci,
        const float* __restrict__ logdt) {
    const int h   = blockIdx.x;
    const int tid = threadIdx.x;

    __shared__ float2 lam[NST], w00[NST], w01[NST], w10[NST];
    __shared__ float  w11[NST];
    __shared__ __align__(16) u64c WT[NST * 14];   // packed a/b weight tables
    extern __shared__ float2 x[];   // SPAD float2

    if (tid < NST) {
        int n = tid;
        lam[n] = make_float2(Lr[n], Li[n]);
        float2 P  = make_float2(Pr[n], Pi[n]);
        float2 Bv = make_float2(Br[n], Bi[n]);
        float2 Cc = make_float2(Cr[h * NST + n], -Ci[h * NST + n]);
        w00[n] = cmul(Cc, Bv);
        w01[n] = cmul(Cc, P);
        float2 Qc = make_float2(P.x, -P.y);
        w10[n] = cmul(Qc, Bv);
        w11[n] = P.x * P.x + P.y * P.y;
    }
    __syncthreads();

    // Build packed tables: for weight w (a-lane index n, b-lane index m=63-n):
    //  WA = (wn.re,  wm.re)   [* RX -> RE]
    //  WB = (-wn.im, wm.im)   [* RY -> RE]
    //  WC = (wn.re, -wm.re)   [* RY -> IM]
    //  WD = (wn.im,  wm.im)   [* RX -> IM]
    if (tid < NST) {
        int n = tid, m = NST - 1 - n;
        u64c* T = &WT[n * 14];
        float2 wn, wm;
        wn = w00[n]; wm = w00[m];
        T[0]  = pk2(wn.x, wm.x);  T[1]  = pk2(-wn.y, wm.y);
        T[2]  = pk2(wn.x, -wm.x); T[3]  = pk2(wn.y, wm.y);
        wn = w01[n]; wm = w01[m];
        T[4]  = pk2(wn.x, wm.x);  T[5]  = pk2(-wn.y, wm.y);
        T[6]  = pk2(wn.x, -wm.x); T[7]  = pk2(wn.y, wm.y);
        wn = w10[n]; wm = w10[m];
        T[8]  = pk2(wn.x, wm.x);  T[9]  = pk2(-wn.y, wm.y);
        T[10] = pk2(wn.x, -wm.x); T[11] = pk2(wn.y, wm.y);
        T[12] = pk2(w11[n], w11[m]);
        T[13] = pk2(w11[n], -w11[m]);
    }
    __syncthreads();

    const float dt = expf(logdt[h]);
    const float g0 = 2.0f / dt;

    // ---- at_roots into x[0..2047] (natural order), pairing l with 2048-l ----
    for (int l = tid; l < 1024; l += blockDim.x) {
        float ss, cc;
        sincospif((float)l * (1.0f / 1024.0f), &ss, &cc);
        float2 om = make_float2(cc, -ss);
        float2 den = make_float2(1.f + om.x, om.y);
        float2 num = make_float2(1.f - om.x, -om.y);
        float idl  = __fdividef(1.f, den.x * den.x + den.y * den.y);
        float2 c2  = make_float2(2.f * den.x * idl, -2.f * den.y * idl);
        float2 gf  = cmul(num, make_float2(den.x, -den.y));
        float2 g   = make_float2(g0 * gf.x * idl, g0 * gf.y * idl);

        // packed accumulators: lane0 = a-side, lane1 = b-side
        u64c K00R = 0, K00I = 0, K01R = 0, K01I = 0;
        u64c K10R = 0, K10I = 0, K11R = 0, K11I = 0;
#pragma unroll 4
        for (int n = 0; n < NST; n++) {
            float2 L = lam[n];
            float dx = g.x - L.x;
            float dy = g.y - L.y;
            float iv = __fdividef(1.f, fmaf(dx, dx, dy * dy));
            float rx = dx * iv;
            float ry = -dy * iv;                      // r = rx + i*ry
            u64c RX = pk2(rx, rx);
            u64c RY = pk2(ry, ry);
            const u64c* T = &WT[n * 14];
            ulonglong2 t0 = *(const ulonglong2*)(T + 0);
            ulonglong2 t1 = *(const ulonglong2*)(T + 2);
            ulonglong2 t2 = *(const ulonglong2*)(T + 4);
            ulonglong2 t3 = *(const ulonglong2*)(T + 6);
            ulonglong2 t4 = *(const ulonglong2*)(T + 8);
            ulonglong2 t5 = *(const ulonglong2*)(T + 10);
            ulonglong2 t6 = *(const ulonglong2*)(T + 12);
            K00R = ffma2_(t0.x, RX, K00R);  K00R = ffma2_(t0.y, RY, K00R);
            K00I = ffma2_(t1.x, RY, K00I);  K00I = ffma2_(t1.y, RX, K00I);
            K01R = ffma2_(t2.x, RX, K01R);  K01R = ffma2_(t2.y, RY, K01R);
            K01I = ffma2_(t3.x, RY, K01I);  K01I = ffma2_(t3.y, RX, K01I);
            K10R = ffma2_(t4.x, RX, K10R);  K10R = ffma2_(t4.y, RY, K10R);
            K10I = ffma2_(t5.x, RY, K10I);  K10I = ffma2_(t5.y, RX, K10I);
            K11R = ffma2_(t6.x, RX, K11R);
            K11I = ffma2_(t6.y, RY, K11I);
        }
        // unpack (a,b) lanes
        float2 r00 = unpk2(K00R), i00 = unpk2(K00I);
        float2 r01 = unpk2(K01R), i01 = unpk2(K01I);
        float2 r10 = unpk2(K10R), i10 = unpk2(K10I);
        float2 r11 = unpk2(K11R), i11 = unpk2(K11I);
        float2 a00 = make_float2(r00.x, i00.x), b00 = make_float2(r00.y, i00.y);
        float2 a01 = make_float2(r01.x, i01.x), b01 = make_float2(r01.y, i01.y);
        float2 a10 = make_float2(r10.x, i10.x), b10 = make_float2(r10.y, i10.y);
        float2 a11 = make_float2(r11.x, i11.x), b11 = make_float2(r11.y, i11.y);

        {   // A[l]
            float2 onep = make_float2(1.f + a11.x, a11.y);
            float  ip   = __fdividef(1.f, onep.x * onep.x + onep.y * onep.y);
            float2 invd = make_float2(onep.x * ip, -onep.y * ip);
            float2 t2   = cmul(cmul(a01, a10), invd);
            x[SIDX(l)]  = cmul(c2, csub(a00, t2));
        }
        if (l != 0) {   // A[2048-l], c2' = conj(c2)
            float2 c2c  = make_float2(c2.x, -c2.y);
            float2 onep = make_float2(1.f + b11.x, b11.y);
            float  ip   = __fdividef(1.f, onep.x * onep.x + onep.y * onep.y);
            float2 invd = make_float2(onep.x * ip, -onep.y * ip);
            float2 t2   = cmul(cmul(b01, b10), invd);
            x[SIDX(2048 - l)] = cmul(c2c, csub(b00, t2));
        }
    }
    if (tid == 0) {
        // l = 1024: omega = -1, analytic limit: at -> dt * sum(w00) / 2
        float2 s = make_float2(0.f, 0.f);
        for (int n = 0; n < NST; n++) s = cadd(s, w00[n]);
        x[SIDX(1024)] = make_float2(0.5f * dt * s.x, 0.5f * dt * s.y);
    }
    __syncthreads();

    // ---- inverse FFT 2048 (radix-2 DIF, conj tw): natural -> bit-reversed ----
    {
        int step = 2;
        for (int mh = 1024; mh >= 1; mh >>= 1, step <<= 1) {
            for (int t = tid; t < 1024; t += blockDim.x) {
                int k  = t & (mh - 1);
                int i0 = 2 * t - k, i1 = i0 + mh;
                float2 a = x[SIDX(i0)], b = x[SIDX(i1)];
                x[SIDX(i0)] = cadd(a, b);
                x[SIDX(i1)] = cmul(csub(a, b), tw4096c(k * step));
            }
            __syncthreads();
        }
    }
    // bit-reverse (11-bit) to natural order
    for (int i = tid; i < 2048; i += blockDim.x) {
        int r = __brev(i) >> 21;
        if (r > i) { float2 t = x[SIDX(i)]; x[SIDX(i)] = x[SIDX(r)]; x[SIDX(r)] = t; }
    }
    __syncthreads();
    const float sc = 1.0f / 2048.0f;
    for (int i = tid; i < 2048; i += blockDim.x) {
        float2 t = x[SIDX(i)];
        x[SIDX(i)] = make_float2(t.x * sc, 0.f);
    }
    for (int i = 2048 + tid; i < NFFT; i += blockDim.x) x[SIDX(i)] = make_float2(0.f, 0.f);
    __syncthreads();

    // ---- forward FFT 4096: 3 register-radix-16 passes ----
    float2 v[16];
#pragma unroll
    for (int j = 0; j < 16; j++) v[j] = x[SIDX(tid + 256 * j)];
    fwd16(v, tw4096(tid));
#pragma unroll
    for (int j = 0; j < 16; j++) x[SIDX(tid + 256 * j)] = v[j];
    __syncthreads();

    const int base2 = ((tid >> 4) << 8) + (tid & 15);
#pragma unroll
    for (int j = 0; j < 16; j++) v[j] = x[SIDX(base2 + 16 * j)];
    fwd16(v, tw4096((tid & 15) << 4));
#pragma unroll
    for (int j = 0; j < 16; j++) x[SIDX(base2 + 16 * j)] = v[j];
    __syncthreads();

#pragma unroll
    for (int j = 0; j < 16; j++) v[j] = x[SIDX(16 * tid + j)];
    fwd16(v, make_float2(1.f, 0.f));

    // store in conv-friendly layout: d_Kf[h][j*256 + tid] (coalesced)
    float2* kf = d_Kf + (size_t)h * NFFT;
#pragma unroll
    for (int j = 0; j < 16; j++) kf[j * 256 + tid] = v[j];
}

// ---------------------------------------------------------------------------
// Kernel C: channel-pair x batch-pair FFT convolution + skip (R10-exact).
// ---------------------------------------------------------------------------
__global__ void __launch_bounds__(256, 2) kernel_conv(
        const float* __restrict__ u, const float* __restrict__ D,
        float* __restrict__ y) {
    const int hp = blockIdx.x;                 // channel pair (2hp, 2hp+1)
    const int bp = blockIdx.y;                 // batch pair (2bp, 2bp+1)
    const int t  = threadIdx.x;
    extern __shared__ float2 x[];   // SPAD float2

    const float2* ua2 = (const float2*)(u + (size_t)(2 * bp) * LSEQ * HCH) + hp;
    const float2* ub2 = (const float2*)(u + (size_t)(2 * bp + 1) * LSEQ * HCH) + hp;

    float2 v[16], z1[8], y0[8];
#pragma unroll
    for (int j = 0; j < 8; j++) {
        size_t idx = (size_t)(t + 256 * j) * (HCH / 2);
        float2 la = ua2[idx];
        float2 lb = ub2[idx];
        v[j]  = make_float2(la.x, lb.x);       // channel 2hp:   b0 + i*b1
        z1[j] = make_float2(la.y, lb.y);       // channel 2hp+1: b0 + i*b1
    }
#pragma unroll
    for (int j = 8; j < 16; j++) v[j] = make_float2(0.f, 0.f);

    const float2 w1  = tw4096(t);
    const float2 wp2 = tw4096((t & 15) << 4);
    const int base2  = ((t >> 4) << 8) + (t & 15);

    fft_conv_4096(v, x, t, base2, w1, wp2, d_Kf + (size_t)(2 * hp) * NFFT);
#pragma unroll
    for (int j = 0; j < 8; j++) y0[j] = v[j];

#pragma unroll
    for (int j = 0; j < 8; j++) v[j] = z1[j];
#pragma unroll
    for (int j = 8; j < 16; j++) v[j] = make_float2(0.f, 0.f);
    fft_conv_4096(v, x, t, base2, w1, wp2, d_Kf + (size_t)(2 * hp + 1) * NFFT);

    const float D0  = D[2 * hp];
    const float D1  = D[2 * hp + 1];
    const float inv = 1.0f / (float)NFFT;
    float2* ya2 = (float2*)(y + (size_t)(2 * bp) * LSEQ * HCH) + hp;
    float2* yb2 = (float2*)(y + (size_t)(2 * bp + 1) * LSEQ * HCH) + hp;
#pragma unroll
    for (int j = 0; j < 8; j++) {
        size_t idx = (size_t)(t + 256 * j) * (HCH / 2);
        float2 la = ua2[idx];
        float2 lb = ub2[idx];
        float2 oa, ob;
        oa.x = fmaf(y0[j].x, inv, la.x * D0);
        oa.y = fmaf(v[j].x,  inv, la.y * D1);
        ob.x = fmaf(y0[j].y, inv, lb.x * D0);
        ob.y = fmaf(v[j].y,  inv, lb.y * D1);
        ya2[idx] = oa;
        yb2[idx] = ob;
    }
}

// ---------------------------------------------------------------------------
extern "C" void kernel_launch(void* const* d_in, const int* in_sizes, int n_in,
                              void* d_out, int out_size) {
    const float* u   = (const float*)d_in[0];
    const float* Lr  = (const float*)d_in[1];
    const float* Li  = (const float*)d_in[2];
    const float* Pr  = (const float*)d_in[3];
    const float* Pi  = (const float*)d_in[4];
    const float* Br  = (const float*)d_in[5];
    const float* Bi  = (const float*)d_in[6];
    const float* Cr  = (const float*)d_in[7];
    const float* Ci  = (const float*)d_in[8];
    const float* ldt = (const float*)d_in[9];
    const float* D   = (const float*)d_in[10];
    float* y = (float*)d_out;

    const size_t smem = (size_t)SPAD * sizeof(float2);   // 34816 B

    kernel_spec<<<HCH, 256, smem>>>(Lr, Li, Pr, Pi, Br, Bi, Cr, Ci, ldt);
    kernel_conv<<<dim3(HCH / 2, BS / 2), 256, smem>>>(u, D, y);
}

// round 12
// speedup vs baseline: 1.2619x; 1.0203x over previous
#include <cuda_runtime.h>
#include <math.h>

#define HCH  512
#define NST  64
#define BS   8
#define LSEQ 2048
#define NFFT 4096
#define SIDX(i) ((i) + ((i) >> 4))
#define SPAD (NFFT + (NFFT >> 4))   // 4352 float2 = 34816 B

// per-channel spectrum, layout [h][j*256 + t] holding bit-rev position p=16t+j
__device__ float2 d_Kf[(size_t)HCH * NFFT];
// per-channel ready flags (reset every launch by zero_flags)
__device__ int d_flags[HCH];

// W16^m = exp(-2*pi*i*m/16), m=0..7
__constant__ float2 C16[8] = {
    { 1.0f,           0.0f},
    { 0.92387953251f, -0.38268343236f},
    { 0.70710678119f, -0.70710678119f},
    { 0.38268343236f, -0.92387953251f},
    { 0.0f,          -1.0f},
    {-0.38268343236f, -0.92387953251f},
    {-0.70710678119f, -0.70710678119f},
    {-0.92387953251f, -0.38268343236f},
};

typedef unsigned long long u64c;

// ---- packed f32x2 helpers (sm_100a) ----
__device__ __forceinline__ u64c pk2(float lo, float hi) {
    u64c r; asm("mov.b64 %0, {%1, %2};" : "=l"(r) : "f"(lo), "f"(hi)); return r;
}
__device__ __forceinline__ float2 unpk2(u64c v) {
    float lo, hi; asm("mov.b64 {%0, %1}, %2;" : "=f"(lo), "=f"(hi) : "l"(v));
    return make_float2(lo, hi);
}
__device__ __forceinline__ u64c ffma2_(u64c a, u64c b, u64c c) {
    u64c r; asm("fma.rn.f32x2 %0, %1, %2, %3;" : "=l"(r) : "l"(a), "l"(b), "l"(c));
    return r;
}

__device__ __forceinline__ float2 cmul(float2 a, float2 b) {
    return make_float2(fmaf(a.x, b.x, -a.y * b.y), fmaf(a.x, b.y, a.y * b.x));
}
__device__ __forceinline__ float2 cmulj(float2 a, float2 b) {   // a * conj(b)
    return make_float2(fmaf(a.x, b.x, a.y * b.y), fmaf(a.y, b.x, -a.x * b.y));
}
__device__ __forceinline__ float2 cadd(float2 a, float2 b) { return make_float2(a.x + b.x, a.y + b.y); }
__device__ __forceinline__ float2 csub(float2 a, float2 b) { return make_float2(a.x - b.x, a.y - b.y); }

__device__ __forceinline__ float2 tw4096(int j) {
    float s, c;
    sincospif((float)j * (1.0f / 2048.0f), &s, &c);
    return make_float2(c, -s);
}
__device__ __forceinline__ float2 tw4096c(int j) {
    float s, c;
    sincospif((float)j * (1.0f / 2048.0f), &s, &c);
    return make_float2(c, s);
}

// ---------------------------------------------------------------------------
// 16-point register FFT blocks (3 passes = full radix-2 DIF; position p ends
// holding frequency brev12(p)).
// ---------------------------------------------------------------------------
__device__ __forceinline__ void fwd16(float2* v, float2 w1) {
    float2 w2 = cmul(w1, w1), w4 = cmul(w2, w2), w8 = cmul(w4, w4);
#pragma unroll
    for (int j = 0; j < 8; j++) {
        float2 tw = cmul(w1, C16[j]);
        float2 a = v[j], bb = v[j + 8];
        v[j] = cadd(a, bb);
        v[j + 8] = cmul(csub(a, bb), tw);
    }
#pragma unroll
    for (int g = 0; g < 16; g += 8)
#pragma unroll
        for (int j = 0; j < 4; j++) {
            float2 tw = cmul(w2, C16[2 * j]);
            float2 a = v[g + j], bb = v[g + j + 4];
            v[g + j] = cadd(a, bb);
            v[g + j + 4] = cmul(csub(a, bb), tw);
        }
#pragma unroll
    for (int g = 0; g < 16; g += 4)
#pragma unroll
        for (int j = 0; j < 2; j++) {
            float2 tw = cmul(w4, C16[4 * j]);
            float2 a = v[g + j], bb = v[g + j + 2];
            v[g + j] = cadd(a, bb);
            v[g + j + 2] = cmul(csub(a, bb), tw);
        }
#pragma unroll
    for (int g = 0; g < 16; g += 2) {
        float2 a = v[g], bb = v[g + 1];
        v[g] = cadd(a, bb);
        v[g + 1] = cmul(csub(a, bb), w8);
    }
}

__device__ __forceinline__ void inv16(float2* v, float2 w1) {
    float2 c1 = make_float2(w1.x, -w1.y);
    float2 c2 = cmul(c1, c1), c4 = cmul(c2, c2), c8 = cmul(c4, c4);
#pragma unroll
    for (int g = 0; g < 16; g += 2) {
        float2 tb = cmul(v[g + 1], c8);
        float2 a = v[g];
        v[g] = cadd(a, tb);
        v[g + 1] = csub(a, tb);
    }
#pragma unroll
    for (int g = 0; g < 16; g += 4)
#pragma unroll
        for (int j = 0; j < 2; j++) {
            float2 tw = cmulj(c4, C16[4 * j]);
            float2 tb = cmul(v[g + j + 2], tw);
            float2 a = v[g + j];
            v[g + j] = cadd(a, tb);
            v[g + j + 2] = csub(a, tb);
        }
#pragma unroll
    for (int g = 0; g < 16; g += 8)
#pragma unroll
        for (int j = 0; j < 4; j++) {
            float2 tw = cmulj(c2, C16[2 * j]);
            float2 tb = cmul(v[g + j + 4], tw);
            float2 a = v[g + j];
            v[g + j] = cadd(a, tb);
            v[g + j + 4] = csub(a, tb);
        }
#pragma unroll
    for (int j = 0; j < 8; j++) {
        float2 tw = cmulj(c1, C16[j]);
        float2 tb = cmul(v[j + 8], tw);
        float2 a = v[j];
        v[j] = cadd(a, tb);
        v[j + 8] = csub(a, tb);
    }
}

// One full 4096 FFT-conv-IFFT on v[16] through smem x.
__device__ __forceinline__ void fft_conv_4096(
        float2* v, float2* x, int t, int base2,
        float2 w1, float2 wp2, const float2* __restrict__ kf) {
    fwd16(v, w1);
#pragma unroll
    for (int j = 0; j < 16; j++) x[SIDX(t + 256 * j)] = v[j];
    __syncthreads();
#pragma unroll
    for (int j = 0; j < 16; j++) v[j] = x[SIDX(base2 + 16 * j)];
    fwd16(v, wp2);
#pragma unroll
    for (int j = 0; j < 16; j++) x[SIDX(base2 + 16 * j)] = v[j];
    __syncthreads();
#pragma unroll
    for (int j = 0; j < 16; j++) v[j] = x[SIDX(16 * t + j)];
    fwd16(v, make_float2(1.f, 0.f));
#pragma unroll
    for (int j = 0; j < 16; j++) v[j] = cmul(v[j], kf[j * 256 + t]);
    inv16(v, make_float2(1.f, 0.f));
#pragma unroll
    for (int j = 0; j < 16; j++) x[SIDX(16 * t + j)] = v[j];
    __syncthreads();
#pragma unroll
    for (int j = 0; j < 16; j++) v[j] = x[SIDX(base2 + 16 * j)];
    inv16(v, wp2);
#pragma unroll
    for (int j = 0; j < 16; j++) x[SIDX(base2 + 16 * j)] = v[j];
    __syncthreads();
#pragma unroll
    for (int j = 0; j < 16; j++) v[j] = x[SIDX(t + 256 * j)];
    inv16(v, w1);
}

// ---------------------------------------------------------------------------
// Flag reset (every launch / graph replay)
// ---------------------------------------------------------------------------
__global__ void zero_flags() {
    if (threadIdx.x < HCH) d_flags[threadIdx.x] = 0;
}

// ---------------------------------------------------------------------------
// Fused kernel: bids [0, HCH) = spec(channel h=bid) -> set flag;
//               bids [HCH, HCH+1024) = conv(hp = i&255, bp = i>>8), waits on
//               flags[2hp], flags[2hp+1]. Dispatch is bid-ordered and spec
//               CTAs never wait => no deadlock; conv spin time ~0.
// ---------------------------------------------------------------------------
__global__ void __launch_bounds__(256, 2) fused_kernel(
        const float* __restrict__ u,
        const float* __restrict__ Lr, const float* __restrict__ Li,
        const float* __restrict__ Pr, const float* __restrict__ Pi,
        const float* __restrict__ Br, const float* __restrict__ Bi,
        const float* __restrict__ Cr, const float* __restrict__ Ci,
        const float* __restrict__ logdt, const float* __restrict__ D,
        float* __restrict__ y) {
    extern __shared__ float2 x[];   // SPAD float2

    if (blockIdx.x < HCH) {
        // ================= SPEC branch =================
        const int h   = blockIdx.x;
        const int tid = threadIdx.x;

        __shared__ float2 lam[NST], w00[NST];
        __shared__ __align__(16) u64c WT[NST * 14];

        if (tid < NST) {
            int n = tid;
            lam[n] = make_float2(Lr[n], Li[n]);
            float2 P  = make_float2(Pr[n], Pi[n]);
            float2 Bv = make_float2(Br[n], Bi[n]);
            float2 Cc = make_float2(Cr[h * NST + n], -Ci[h * NST + n]);
            w00[n] = cmul(Cc, Bv);
        }
        __syncthreads();
        // Build packed a/b weight tables (a-lane n, b-lane m=63-n)
        if (tid < NST) {
            int n = tid, m = NST - 1 - n;
            u64c* T = &WT[n * 14];
            // recompute weights for both n and m locally
            float2 Pn = make_float2(Pr[n], Pi[n]);
            float2 Pm = make_float2(Pr[m], Pi[m]);
            float2 Bn = make_float2(Br[n], Bi[n]);
            float2 Bm = make_float2(Br[m], Bi[m]);
            float2 Ccn = make_float2(Cr[h * NST + n], -Ci[h * NST + n]);
            float2 Ccm = make_float2(Cr[h * NST + m], -Ci[h * NST + m]);
            float2 wn, wm;
            wn = cmul(Ccn, Bn); wm = cmul(Ccm, Bm);          // w00
            T[0]  = pk2(wn.x, wm.x);  T[1]  = pk2(-wn.y, wm.y);
            T[2]  = pk2(wn.x, -wm.x); T[3]  = pk2(wn.y, wm.y);
            wn = cmul(Ccn, Pn); wm = cmul(Ccm, Pm);          // w01
            T[4]  = pk2(wn.x, wm.x);  T[5]  = pk2(-wn.y, wm.y);
            T[6]  = pk2(wn.x, -wm.x); T[7]  = pk2(wn.y, wm.y);
            float2 Qcn = make_float2(Pn.x, -Pn.y);
            float2 Qcm = make_float2(Pm.x, -Pm.y);
            wn = cmul(Qcn, Bn); wm = cmul(Qcm, Bm);          // w10
            T[8]  = pk2(wn.x, wm.x);  T[9]  = pk2(-wn.y, wm.y);
            T[10] = pk2(wn.x, -wm.x); T[11] = pk2(wn.y, wm.y);
            float w11n = Pn.x * Pn.x + Pn.y * Pn.y;
            float w11m = Pm.x * Pm.x + Pm.y * Pm.y;
            T[12] = pk2(w11n, w11m);
            T[13] = pk2(w11n, -w11m);
        }
        __syncthreads();

        const float dt = expf(logdt[h]);
        const float g0 = 2.0f / dt;

        for (int l = tid; l < 1024; l += blockDim.x) {
            float ss, cc;
            sincospif((float)l * (1.0f / 1024.0f), &ss, &cc);
            float2 om = make_float2(cc, -ss);
            float2 den = make_float2(1.f + om.x, om.y);
            float2 num = make_float2(1.f - om.x, -om.y);
            float idl  = __fdividef(1.f, den.x * den.x + den.y * den.y);
            float2 c2  = make_float2(2.f * den.x * idl, -2.f * den.y * idl);
            float2 gf  = cmul(num, make_float2(den.x, -den.y));
            float2 g   = make_float2(g0 * gf.x * idl, g0 * gf.y * idl);

            u64c K00R = 0, K00I = 0, K01R = 0, K01I = 0;
            u64c K10R = 0, K10I = 0, K11R = 0, K11I = 0;
#pragma unroll 4
            for (int n = 0; n < NST; n++) {
                float2 L = lam[n];
                float dx = g.x - L.x;
                float dy = g.y - L.y;
                float iv = __fdividef(1.f, fmaf(dx, dx, dy * dy));
                float rx = dx * iv;
                float ry = -dy * iv;
                u64c RX = pk2(rx, rx);
                u64c RY = pk2(ry, ry);
                const u64c* T = &WT[n * 14];
                ulonglong2 t0 = *(const ulonglong2*)(T + 0);
                ulonglong2 t1 = *(const ulonglong2*)(T + 2);
                ulonglong2 t2 = *(const ulonglong2*)(T + 4);
                ulonglong2 t3 = *(const ulonglong2*)(T + 6);
                ulonglong2 t4 = *(const ulonglong2*)(T + 8);
                ulonglong2 t5 = *(const ulonglong2*)(T + 10);
                ulonglong2 t6 = *(const ulonglong2*)(T + 12);
                K00R = ffma2_(t0.x, RX, K00R);  K00R = ffma2_(t0.y, RY, K00R);
                K00I = ffma2_(t1.x, RY, K00I);  K00I = ffma2_(t1.y, RX, K00I);
                K01R = ffma2_(t2.x, RX, K01R);  K01R = ffma2_(t2.y, RY, K01R);
                K01I = ffma2_(t3.x, RY, K01I);  K01I = ffma2_(t3.y, RX, K01I);
                K10R = ffma2_(t4.x, RX, K10R);  K10R = ffma2_(t4.y, RY, K10R);
                K10I = ffma2_(t5.x, RY, K10I);  K10I = ffma2_(t5.y, RX, K10I);
                K11R = ffma2_(t6.x, RX, K11R);
                K11I = ffma2_(t6.y, RY, K11I);
            }
            float2 r00 = unpk2(K00R), i00 = unpk2(K00I);
            float2 r01 = unpk2(K01R), i01 = unpk2(K01I);
            float2 r10 = unpk2(K10R), i10 = unpk2(K10I);
            float2 r11 = unpk2(K11R), i11 = unpk2(K11I);
            float2 a00 = make_float2(r00.x, i00.x), b00 = make_float2(r00.y, i00.y);
            float2 a01 = make_float2(r01.x, i01.x), b01 = make_float2(r01.y, i01.y);
            float2 a10 = make_float2(r10.x, i10.x), b10 = make_float2(r10.y, i10.y);
            float2 a11 = make_float2(r11.x, i11.x), b11 = make_float2(r11.y, i11.y);

            {   // A[l]
                float2 onep = make_float2(1.f + a11.x, a11.y);
                float  ip   = __fdividef(1.f, onep.x * onep.x + onep.y * onep.y);
                float2 invd = make_float2(onep.x * ip, -onep.y * ip);
                float2 t2   = cmul(cmul(a01, a10), invd);
                x[SIDX(l)]  = cmul(c2, csub(a00, t2));
            }
            if (l != 0) {   // A[2048-l]
                float2 c2c  = make_float2(c2.x, -c2.y);
                float2 onep = make_float2(1.f + b11.x, b11.y);
                float  ip   = __fdividef(1.f, onep.x * onep.x + onep.y * onep.y);
                float2 invd = make_float2(onep.x * ip, -onep.y * ip);
                float2 t2   = cmul(cmul(b01, b10), invd);
                x[SIDX(2048 - l)] = cmul(c2c, csub(b00, t2));
            }
        }
        if (tid == 0) {
            float2 s = make_float2(0.f, 0.f);
            for (int n = 0; n < NST; n++) s = cadd(s, w00[n]);
            x[SIDX(1024)] = make_float2(0.5f * dt * s.x, 0.5f * dt * s.y);
        }
        __syncthreads();

        // inverse FFT 2048 (radix-2 DIF, conj tw): natural -> bit-reversed
        {
            int step = 2;
            for (int mh = 1024; mh >= 1; mh >>= 1, step <<= 1) {
                for (int t = tid; t < 1024; t += blockDim.x) {
                    int k  = t & (mh - 1);
                    int i0 = 2 * t - k, i1 = i0 + mh;
                    float2 a = x[SIDX(i0)], b = x[SIDX(i1)];
                    x[SIDX(i0)] = cadd(a, b);
                    x[SIDX(i1)] = cmul(csub(a, b), tw4096c(k * step));
                }
                __syncthreads();
            }
        }
        for (int i = tid; i < 2048; i += blockDim.x) {
            int r = __brev(i) >> 21;
            if (r > i) { float2 t = x[SIDX(i)]; x[SIDX(i)] = x[SIDX(r)]; x[SIDX(r)] = t; }
        }
        __syncthreads();
        const float sc = 1.0f / 2048.0f;
        for (int i = tid; i < 2048; i += blockDim.x) {
            float2 t = x[SIDX(i)];
            x[SIDX(i)] = make_float2(t.x * sc, 0.f);
        }
        for (int i = 2048 + tid; i < NFFT; i += blockDim.x) x[SIDX(i)] = make_float2(0.f, 0.f);
        __syncthreads();

        // forward FFT 4096: 3 register-radix-16 passes
        float2 v[16];
#pragma unroll
        for (int j = 0; j < 16; j++) v[j] = x[SIDX(tid + 256 * j)];
        fwd16(v, tw4096(tid));
#pragma unroll
        for (int j = 0; j < 16; j++) x[SIDX(tid + 256 * j)] = v[j];
        __syncthreads();

        const int base2 = ((tid >> 4) << 8) + (tid & 15);
#pragma unroll
        for (int j = 0; j < 16; j++) v[j] = x[SIDX(base2 + 16 * j)];
        fwd16(v, tw4096((tid & 15) << 4));
#pragma unroll
        for (int j = 0; j < 16; j++) x[SIDX(base2 + 16 * j)] = v[j];
        __syncthreads();

#pragma unroll
        for (int j = 0; j < 16; j++) v[j] = x[SIDX(16 * tid + j)];
        fwd16(v, make_float2(1.f, 0.f));

        float2* kf = d_Kf + (size_t)h * NFFT;
#pragma unroll
        for (int j = 0; j < 16; j++) kf[j * 256 + tid] = v[j];

        // release: all Kf stores done -> publish flag
        __syncthreads();
        if (tid == 0) {
            __threadfence();
            atomicExch(&d_flags[h], 1);
        }
    } else {
        // ================= CONV branch =================
        const int i  = blockIdx.x - HCH;
        const int hp = i & (HCH / 2 - 1);      // 0..255
        const int bp = i >> 8;                 // 0..3
        const int t  = threadIdx.x;

        // acquire: wait for both channels' spectra
        if (t == 0) {
            while (atomicAdd(&d_flags[2 * hp], 0) == 0) __nanosleep(200);
            while (atomicAdd(&d_flags[2 * hp + 1], 0) == 0) __nanosleep(200);
            __threadfence();
        }
        __syncthreads();

        const float2* ua2 = (const float2*)(u + (size_t)(2 * bp) * LSEQ * HCH) + hp;
        const float2* ub2 = (const float2*)(u + (size_t)(2 * bp + 1) * LSEQ * HCH) + hp;

        float2 v[16], z1[8], y0[8];
#pragma unroll
        for (int j = 0; j < 8; j++) {
            size_t idx = (size_t)(t + 256 * j) * (HCH / 2);
            float2 la = ua2[idx];
            float2 lb = ub2[idx];
            v[j]  = make_float2(la.x, lb.x);   // channel 2hp:   b0 + i*b1
            z1[j] = make_float2(la.y, lb.y);   // channel 2hp+1: b0 + i*b1
        }
#pragma unroll
        for (int j = 8; j < 16; j++) v[j] = make_float2(0.f, 0.f);

        const float2 w1  = tw4096(t);
        const float2 wp2 = tw4096((t & 15) << 4);
        const int base2  = ((t >> 4) << 8) + (t & 15);

        fft_conv_4096(v, x, t, base2, w1, wp2, d_Kf + (size_t)(2 * hp) * NFFT);
#pragma unroll
        for (int j = 0; j < 8; j++) y0[j] = v[j];

#pragma unroll
        for (int j = 0; j < 8; j++) v[j] = z1[j];
#pragma unroll
        for (int j = 8; j < 16; j++) v[j] = make_float2(0.f, 0.f);
        fft_conv_4096(v, x, t, base2, w1, wp2, d_Kf + (size_t)(2 * hp + 1) * NFFT);

        const float D0  = D[2 * hp];
        const float D1  = D[2 * hp + 1];
        const float inv = 1.0f / (float)NFFT;
        float2* ya2 = (float2*)(y + (size_t)(2 * bp) * LSEQ * HCH) + hp;
        float2* yb2 = (float2*)(y + (size_t)(2 * bp + 1) * LSEQ * HCH) + hp;
#pragma unroll
        for (int j = 0; j < 8; j++) {
            size_t idx = (size_t)(t + 256 * j) * (HCH / 2);
            float2 la = ua2[idx];
            float2 lb = ub2[idx];
            float2 oa, ob;
            oa.x = fmaf(y0[j].x, inv, la.x * D0);
            oa.y = fmaf(v[j].x,  inv, la.y * D1);
            ob.x = fmaf(y0[j].y, inv, lb.x * D0);
            ob.y = fmaf(v[j].y,  inv, lb.y * D1);
            ya2[idx] = oa;
            yb2[idx] = ob;
        }
    }
}

// ---------------------------------------------------------------------------
extern "C" void kernel_launch(void* const* d_in, const int* in_sizes, int n_in,
                              void* d_out, int out_size) {
    const float* u   = (const float*)d_in[0];
    const float* Lr  = (const float*)d_in[1];
    const float* Li  = (const float*)d_in[2];
    const float* Pr  = (const float*)d_in[3];
    const float* Pi  = (const float*)d_in[4];
    const float* Br  = (const float*)d_in[5];
    const float* Bi  = (const float*)d_in[6];
    const float* Cr  = (const float*)d_in[7];
    const float* Ci  = (const float*)d_in[8];
    const float* ldt = (const float*)d_in[9];
    const float* D   = (const float*)d_in[10];
    float* y = (float*)d_out;

    const size_t smem = (size_t)SPAD * sizeof(float2);   // 34816 B

    zero_flags<<<1, HCH>>>();
    fused_kernel<<<HCH + (HCH / 2) * (BS / 2), 256, smem>>>(
        u, Lr, Li, Pr, Pi, Br, Bi, Cr, Ci, ldt, D, y);
}

// round 13
// speedup vs baseline: 1.3176x; 1.0442x over previous
#include <cuda_runtime.h>
#include <math.h>

#define HCH  512
#define NST  64
#define BS   8
#define LSEQ 2048
#define NFFT 4096
#define SIDX(i) ((i) + ((i) >> 4))
#define SPAD (NFFT + (NFFT >> 4))   // 4352 float2 = 34816 B

// per-channel spectrum, layout [h][j*256 + t] holding bit-rev position p=16t+j
__device__ float2 d_Kf[(size_t)HCH * NFFT];
// per-channel ready flags (reset every launch by zero_flags)
__device__ int d_flags[HCH];

// W16^m = exp(-2*pi*i*m/16), m=0..7
__constant__ float2 C16[8] = {
    { 1.0f,           0.0f},
    { 0.92387953251f, -0.38268343236f},
    { 0.70710678119f, -0.70710678119f},
    { 0.38268343236f, -0.92387953251f},
    { 0.0f,          -1.0f},
    {-0.38268343236f, -0.92387953251f},
    {-0.70710678119f, -0.70710678119f},
    {-0.92387953251f, -0.38268343236f},
};
// W8^m = exp(-2*pi*i*m/8), m=0..3
__constant__ float2 C8[4] = {
    { 1.0f,           0.0f},
    { 0.70710678119f, -0.70710678119f},
    { 0.0f,          -1.0f},
    {-0.70710678119f, -0.70710678119f},
};

typedef unsigned long long u64c;

// ---- packed f32x2 helpers (sm_100a) ----
__device__ __forceinline__ u64c pk2(float lo, float hi) {
    u64c r; asm("mov.b64 %0, {%1, %2};" : "=l"(r) : "f"(lo), "f"(hi)); return r;
}
__device__ __forceinline__ float2 unpk2(u64c v) {
    float lo, hi; asm("mov.b64 {%0, %1}, %2;" : "=f"(lo), "=f"(hi) : "l"(v));
    return make_float2(lo, hi);
}
__device__ __forceinline__ u64c ffma2_(u64c a, u64c b, u64c c) {
    u64c r; asm("fma.rn.f32x2 %0, %1, %2, %3;" : "=l"(r) : "l"(a), "l"(b), "l"(c));
    return r;
}

__device__ __forceinline__ float2 cmul(float2 a, float2 b) {
    return make_float2(fmaf(a.x, b.x, -a.y * b.y), fmaf(a.x, b.y, a.y * b.x));
}
__device__ __forceinline__ float2 cmulj(float2 a, float2 b) {   // a * conj(b)
    return make_float2(fmaf(a.x, b.x, a.y * b.y), fmaf(a.y, b.x, -a.x * b.y));
}
__device__ __forceinline__ float2 cadd(float2 a, float2 b) { return make_float2(a.x + b.x, a.y + b.y); }
__device__ __forceinline__ float2 csub(float2 a, float2 b) { return make_float2(a.x - b.x, a.y - b.y); }

__device__ __forceinline__ float2 tw4096(int j) {
    float s, c;
    sincospif((float)j * (1.0f / 2048.0f), &s, &c);
    return make_float2(c, -s);
}
__device__ __forceinline__ float2 tw2048(int j) {
    float s, c;
    sincospif((float)j * (1.0f / 1024.0f), &s, &c);
    return make_float2(c, -s);
}

// ---------------------------------------------------------------------------
// Register FFT blocks. fwd16/inv16 = 4 radix-2 DIF/DIT stages; fwd8/inv8 = 3.
// Composition of DIF passes => position p holds frequency brev(p).
// ---------------------------------------------------------------------------
__device__ __forceinline__ void fwd16(float2* v, float2 w1) {
    float2 w2 = cmul(w1, w1), w4 = cmul(w2, w2), w8 = cmul(w4, w4);
#pragma unroll
    for (int j = 0; j < 8; j++) {
        float2 tw = cmul(w1, C16[j]);
        float2 a = v[j], bb = v[j + 8];
        v[j] = cadd(a, bb);
        v[j + 8] = cmul(csub(a, bb), tw);
    }
#pragma unroll
    for (int g = 0; g < 16; g += 8)
#pragma unroll
        for (int j = 0; j < 4; j++) {
            float2 tw = cmul(w2, C16[2 * j]);
            float2 a = v[g + j], bb = v[g + j + 4];
            v[g + j] = cadd(a, bb);
            v[g + j + 4] = cmul(csub(a, bb), tw);
        }
#pragma unroll
    for (int g = 0; g < 16; g += 4)
#pragma unroll
        for (int j = 0; j < 2; j++) {
            float2 tw = cmul(w4, C16[4 * j]);
            float2 a = v[g + j], bb = v[g + j + 2];
            v[g + j] = cadd(a, bb);
            v[g + j + 2] = cmul(csub(a, bb), tw);
        }
#pragma unroll
    for (int g = 0; g < 16; g += 2) {
        float2 a = v[g], bb = v[g + 1];
        v[g] = cadd(a, bb);
        v[g + 1] = cmul(csub(a, bb), w8);
    }
}

__device__ __forceinline__ void inv16(float2* v, float2 w1) {
    float2 c1 = make_float2(w1.x, -w1.y);
    float2 c2 = cmul(c1, c1), c4 = cmul(c2, c2), c8 = cmul(c4, c4);
#pragma unroll
    for (int g = 0; g < 16; g += 2) {
        float2 tb = cmul(v[g + 1], c8);
        float2 a = v[g];
        v[g] = cadd(a, tb);
        v[g + 1] = csub(a, tb);
    }
#pragma unroll
    for (int g = 0; g < 16; g += 4)
#pragma unroll
        for (int j = 0; j < 2; j++) {
            float2 tw = cmulj(c4, C16[4 * j]);
            float2 tb = cmul(v[g + j + 2], tw);
            float2 a = v[g + j];
            v[g + j] = cadd(a, tb);
            v[g + j + 2] = csub(a, tb);
        }
#pragma unroll
    for (int g = 0; g < 16; g += 8)
#pragma unroll
        for (int j = 0; j < 4; j++) {
            float2 tw = cmulj(c2, C16[2 * j]);
            float2 tb = cmul(v[g + j + 4], tw);
            float2 a = v[g + j];
            v[g + j] = cadd(a, tb);
            v[g + j + 4] = csub(a, tb);
        }
#pragma unroll
    for (int j = 0; j < 8; j++) {
        float2 tw = cmulj(c1, C16[j]);
        float2 tb = cmul(v[j + 8], tw);
        float2 a = v[j];
        v[j] = cadd(a, tb);
        v[j + 8] = csub(a, tb);
    }
}

__device__ __forceinline__ void inv8(float2* v, float2 w1) {
    float2 c1 = make_float2(w1.x, -w1.y);
    float2 c2 = cmul(c1, c1), c4 = cmul(c2, c2);
#pragma unroll
    for (int g = 0; g < 8; g += 2) {
        float2 tb = cmul(v[g + 1], c4);
        float2 a = v[g];
        v[g] = cadd(a, tb);
        v[g + 1] = csub(a, tb);
    }
#pragma unroll
    for (int g = 0; g < 8; g += 4)
#pragma unroll
        for (int j = 0; j < 2; j++) {
            float2 tw = cmulj(c2, C8[2 * j]);
            float2 tb = cmul(v[g + j + 2], tw);
            float2 a = v[g + j];
            v[g + j] = cadd(a, tb);
            v[g + j + 2] = csub(a, tb);
        }
#pragma unroll
    for (int j = 0; j < 4; j++) {
        float2 tw = cmulj(c1, C8[j]);
        float2 tb = cmul(v[j + 4], tw);
        float2 a = v[j];
        v[j] = cadd(a, tb);
        v[j + 4] = csub(a, tb);
    }
}

// One full 4096 FFT-conv-IFFT on v[16] through smem x.
__device__ __forceinline__ void fft_conv_4096(
        float2* v, float2* x, int t, int base2,
        float2 w1, float2 wp2, const float2* __restrict__ kf) {
    fwd16(v, w1);
#pragma unroll
    for (int j = 0; j < 16; j++) x[SIDX(t + 256 * j)] = v[j];
    __syncthreads();
#pragma unroll
    for (int j = 0; j < 16; j++) v[j] = x[SIDX(base2 + 16 * j)];
    fwd16(v, wp2);
#pragma unroll
    for (int j = 0; j < 16; j++) x[SIDX(base2 + 16 * j)] = v[j];
    __syncthreads();
#pragma unroll
    for (int j = 0; j < 16; j++) v[j] = x[SIDX(16 * t + j)];
    fwd16(v, make_float2(1.f, 0.f));
#pragma unroll
    for (int j = 0; j < 16; j++) v[j] = cmul(v[j], kf[j * 256 + t]);
    inv16(v, make_float2(1.f, 0.f));
#pragma unroll
    for (int j = 0; j < 16; j++) x[SIDX(16 * t + j)] = v[j];
    __syncthreads();
#pragma unroll
    for (int j = 0; j < 16; j++) v[j] = x[SIDX(base2 + 16 * j)];
    inv16(v, wp2);
#pragma unroll
    for (int j = 0; j < 16; j++) x[SIDX(base2 + 16 * j)] = v[j];
    __syncthreads();
#pragma unroll
    for (int j = 0; j < 16; j++) v[j] = x[SIDX(t + 256 * j)];
    inv16(v, w1);
}

// ---------------------------------------------------------------------------
__global__ void zero_flags() {
    if (threadIdx.x < HCH) d_flags[threadIdx.x] = 0;
}

// ---------------------------------------------------------------------------
// Fused kernel: bids [0, HCH) = spec; bids [HCH, HCH+1024) = conv (flag-gated).
// ---------------------------------------------------------------------------
__global__ void __launch_bounds__(256, 2) fused_kernel(
        const float* __restrict__ u,
        const float* __restrict__ Lr, const float* __restrict__ Li,
        const float* __restrict__ Pr, const float* __restrict__ Pi,
        const float* __restrict__ Br, const float* __restrict__ Bi,
        const float* __restrict__ Cr, const float* __restrict__ Ci,
        const float* __restrict__ logdt, const float* __restrict__ D,
        float* __restrict__ y) {
    extern __shared__ float2 x[];   // SPAD float2

    if (blockIdx.x < HCH) {
        // ================= SPEC branch =================
        const int h   = blockIdx.x;
        const int tid = threadIdx.x;

        __shared__ float2 lam[NST], w00[NST];
        __shared__ __align__(16) u64c WT[NST * 14];

        if (tid < NST) {
            int n = tid;
            lam[n] = make_float2(Lr[n], Li[n]);
            float2 P  = make_float2(Pr[n], Pi[n]);
            float2 Bv = make_float2(Br[n], Bi[n]);
            float2 Cc = make_float2(Cr[h * NST + n], -Ci[h * NST + n]);
            w00[n] = cmul(Cc, Bv);
        }
        __syncthreads();
        // Build packed a/b weight tables (a-lane n, b-lane m=63-n)
        if (tid < NST) {
            int n = tid, m = NST - 1 - n;
            u64c* T = &WT[n * 14];
            float2 Pn = make_float2(Pr[n], Pi[n]);
            float2 Pm = make_float2(Pr[m], Pi[m]);
            float2 Bn = make_float2(Br[n], Bi[n]);
            float2 Bm = make_float2(Br[m], Bi[m]);
            float2 Ccn = make_float2(Cr[h * NST + n], -Ci[h * NST + n]);
            float2 Ccm = make_float2(Cr[h * NST + m], -Ci[h * NST + m]);
            float2 wn, wm;
            wn = cmul(Ccn, Bn); wm = cmul(Ccm, Bm);          // w00
            T[0]  = pk2(wn.x, wm.x);  T[1]  = pk2(-wn.y, wm.y);
            T[2]  = pk2(wn.x, -wm.x); T[3]  = pk2(wn.y, wm.y);
            wn = cmul(Ccn, Pn); wm = cmul(Ccm, Pm);          // w01
            T[4]  = pk2(wn.x, wm.x);  T[5]  = pk2(-wn.y, wm.y);
            T[6]  = pk2(wn.x, -wm.x); T[7]  = pk2(wn.y, wm.y);
            float2 Qcn = make_float2(Pn.x, -Pn.y);
            float2 Qcm = make_float2(Pm.x, -Pm.y);
            wn = cmul(Qcn, Bn); wm = cmul(Qcm, Bm);          // w10
            T[8]  = pk2(wn.x, wm.x);  T[9]  = pk2(-wn.y, wm.y);
            T[10] = pk2(wn.x, -wm.x); T[11] = pk2(wn.y, wm.y);
            float w11n = Pn.x * Pn.x + Pn.y * Pn.y;
            float w11m = Pm.x * Pm.x + Pm.y * Pm.y;
            T[12] = pk2(w11n, w11m);
            T[13] = pk2(w11n, -w11m);
        }
        __syncthreads();

        const float dt = expf(logdt[h]);
        const float g0 = 2.0f / dt;

        // ---- at_roots, stored at BIT-REVERSED positions (brev11(l)) ----
        for (int l = tid; l < 1024; l += blockDim.x) {
            float ss, cc;
            sincospif((float)l * (1.0f / 1024.0f), &ss, &cc);
            float2 om = make_float2(cc, -ss);
            float2 den = make_float2(1.f + om.x, om.y);
            float2 num = make_float2(1.f - om.x, -om.y);
            float idl  = __fdividef(1.f, den.x * den.x + den.y * den.y);
            float2 c2  = make_float2(2.f * den.x * idl, -2.f * den.y * idl);
            float2 gf  = cmul(num, make_float2(den.x, -den.y));
            float2 g   = make_float2(g0 * gf.x * idl, g0 * gf.y * idl);

            u64c K00R = 0, K00I = 0, K01R = 0, K01I = 0;
            u64c K10R = 0, K10I = 0, K11R = 0, K11I = 0;
#pragma unroll 4
            for (int n = 0; n < NST; n++) {
                float2 L = lam[n];
                float dx = g.x - L.x;
                float dy = g.y - L.y;
                float iv = __fdividef(1.f, fmaf(dx, dx, dy * dy));
                float rx = dx * iv;
                float ry = -dy * iv;
                u64c RX = pk2(rx, rx);
                u64c RY = pk2(ry, ry);
                const u64c* T = &WT[n * 14];
                ulonglong2 t0 = *(const ulonglong2*)(T + 0);
                ulonglong2 t1 = *(const ulonglong2*)(T + 2);
                ulonglong2 t2 = *(const ulonglong2*)(T + 4);
                ulonglong2 t3 = *(const ulonglong2*)(T + 6);
                ulonglong2 t4 = *(const ulonglong2*)(T + 8);
                ulonglong2 t5 = *(const ulonglong2*)(T + 10);
                ulonglong2 t6 = *(const ulonglong2*)(T + 12);
                K00R = ffma2_(t0.x, RX, K00R);  K00R = ffma2_(t0.y, RY, K00R);
                K00I = ffma2_(t1.x, RY, K00I);  K00I = ffma2_(t1.y, RX, K00I);
                K01R = ffma2_(t2.x, RX, K01R);  K01R = ffma2_(t2.y, RY, K01R);
                K01I = ffma2_(t3.x, RY, K01I);  K01I = ffma2_(t3.y, RX, K01I);
                K10R = ffma2_(t4.x, RX, K10R);  K10R = ffma2_(t4.y, RY, K10R);
                K10I = ffma2_(t5.x, RY, K10I);  K10I = ffma2_(t5.y, RX, K10I);
                K11R = ffma2_(t6.x, RX, K11R);
                K11I = ffma2_(t6.y, RY, K11I);
            }
            float2 r00 = unpk2(K00R), i00 = unpk2(K00I);
            float2 r01 = unpk2(K01R), i01 = unpk2(K01I);
            float2 r10 = unpk2(K10R), i10 = unpk2(K10I);
            float2 r11 = unpk2(K11R), i11 = unpk2(K11I);
            float2 a00 = make_float2(r00.x, i00.x), b00 = make_float2(r00.y, i00.y);
            float2 a01 = make_float2(r01.x, i01.x), b01 = make_float2(r01.y, i01.y);
            float2 a10 = make_float2(r10.x, i10.x), b10 = make_float2(r10.y, i10.y);
            float2 a11 = make_float2(r11.x, i11.x), b11 = make_float2(r11.y, i11.y);

            {   // A[l] -> position brev11(l)
                float2 onep = make_float2(1.f + a11.x, a11.y);
                float  ip   = __fdividef(1.f, onep.x * onep.x + onep.y * onep.y);
                float2 invd = make_float2(onep.x * ip, -onep.y * ip);
                float2 t2   = cmul(cmul(a01, a10), invd);
                int rl = __brev(l) >> 21;
                x[SIDX(rl)] = cmul(c2, csub(a00, t2));
            }
            if (l != 0) {   // A[2048-l] -> position brev11(2048-l)
                float2 c2c  = make_float2(c2.x, -c2.y);
                float2 onep = make_float2(1.f + b11.x, b11.y);
                float  ip   = __fdividef(1.f, onep.x * onep.x + onep.y * onep.y);
                float2 invd = make_float2(onep.x * ip, -onep.y * ip);
                float2 t2   = cmul(cmul(b01, b10), invd);
                int rl = __brev(2048 - l) >> 21;
                x[SIDX(rl)] = cmul(c2c, csub(b00, t2));
            }
        }
        if (tid == 0) {
            // l = 1024: omega = -1 limit; brev11(1024) = 1
            float2 s = make_float2(0.f, 0.f);
            for (int n = 0; n < NST; n++) s = cadd(s, w00[n]);
            x[SIDX(1)] = make_float2(0.5f * dt * s.x, 0.5f * dt * s.y);
        }
        __syncthreads();

        // ---- inverse FFT 2048: 3 register passes (radices 8,16,16 DIT) ----
        // Forward layout was (16 stride128, 16 stride8, 8 stride1) DIF =>
        // inverse order: inv8 {8t+j}, inv16 {128b+r+8j}, inv16 {t+128j}.
        {
            float2 v8[8];
#pragma unroll
            for (int j = 0; j < 8; j++) v8[j] = x[SIDX(8 * tid + j)];
            inv8(v8, make_float2(1.f, 0.f));
#pragma unroll
            for (int j = 0; j < 8; j++) x[SIDX(8 * tid + j)] = v8[j];
        }
        __syncthreads();
        {
            float2 v[16];
            if (tid < 128) {
                int baseB = ((tid >> 3) << 7) + (tid & 7);
#pragma unroll
                for (int j = 0; j < 16; j++) v[j] = x[SIDX(baseB + 8 * j)];
                inv16(v, tw2048(16 * (tid & 7)));
#pragma unroll
                for (int j = 0; j < 16; j++) x[SIDX(baseB + 8 * j)] = v[j];
            }
            __syncthreads();
            if (tid < 128) {
#pragma unroll
                for (int j = 0; j < 16; j++) v[j] = x[SIDX(tid + 128 * j)];
                inv16(v, tw2048(tid));
                // scale + realify, same per-thread addresses (no barrier needed)
                const float sc = 1.0f / 2048.0f;
#pragma unroll
                for (int j = 0; j < 16; j++)
                    x[SIDX(tid + 128 * j)] = make_float2(v[j].x * sc, 0.f);
            }
            // zero pad (disjoint region)
            for (int i = 2048 + tid; i < NFFT; i += blockDim.x)
                x[SIDX(i)] = make_float2(0.f, 0.f);
        }
        __syncthreads();

        // ---- forward FFT 4096: 3 register-radix-16 passes ----
        float2 v[16];
#pragma unroll
        for (int j = 0; j < 16; j++) v[j] = x[SIDX(tid + 256 * j)];
        fwd16(v, tw4096(tid));
#pragma unroll
        for (int j = 0; j < 16; j++) x[SIDX(tid + 256 * j)] = v[j];
        __syncthreads();

        const int base2 = ((tid >> 4) << 8) + (tid & 15);
#pragma unroll
        for (int j = 0; j < 16; j++) v[j] = x[SIDX(base2 + 16 * j)];
        fwd16(v, tw4096((tid & 15) << 4));
#pragma unroll
        for (int j = 0; j < 16; j++) x[SIDX(base2 + 16 * j)] = v[j];
        __syncthreads();

#pragma unroll
        for (int j = 0; j < 16; j++) v[j] = x[SIDX(16 * tid + j)];
        fwd16(v, make_float2(1.f, 0.f));

        float2* kf = d_Kf + (size_t)h * NFFT;
#pragma unroll
        for (int j = 0; j < 16; j++) kf[j * 256 + tid] = v[j];

        // release
        __syncthreads();
        if (tid == 0) {
            __threadfence();
            atomicExch(&d_flags[h], 1);
        }
    } else {
        // ================= CONV branch =================
        const int i  = blockIdx.x - HCH;
        const int hp = i & (HCH / 2 - 1);      // 0..255
        const int bp = i >> 8;                 // 0..3
        const int t  = threadIdx.x;

        if (t == 0) {
            while (atomicAdd(&d_flags[2 * hp], 0) == 0) __nanosleep(200);
            while (atomicAdd(&d_flags[2 * hp + 1], 0) == 0) __nanosleep(200);
            __threadfence();
        }
        __syncthreads();

        const float2* ua2 = (const float2*)(u + (size_t)(2 * bp) * LSEQ * HCH) + hp;
        const float2* ub2 = (const float2*)(u + (size_t)(2 * bp + 1) * LSEQ * HCH) + hp;

        float2 v[16], z1[8], y0[8];
#pragma unroll
        for (int j = 0; j < 8; j++) {
            size_t idx = (size_t)(t + 256 * j) * (HCH / 2);
            float2 la = ua2[idx];
            float2 lb = ub2[idx];
            v[j]  = make_float2(la.x, lb.x);   // channel 2hp:   b0 + i*b1
            z1[j] = make_float2(la.y, lb.y);   // channel 2hp+1: b0 + i*b1
        }
#pragma unroll
        for (int j = 8; j < 16; j++) v[j] = make_float2(0.f, 0.f);

        const float2 w1  = tw4096(t);
        const float2 wp2 = tw4096((t & 15) << 4);
        const int base2  = ((t >> 4) << 8) + (t & 15);

        fft_conv_4096(v, x, t, base2, w1, wp2, d_Kf + (size_t)(2 * hp) * NFFT);
#pragma unroll
        for (int j = 0; j < 8; j++) y0[j] = v[j];

#pragma unroll
        for (int j = 0; j < 8; j++) v[j] = z1[j];
#pragma unroll
        for (int j = 8; j < 16; j++) v[j] = make_float2(0.f, 0.f);
        fft_conv_4096(v, x, t, base2, w1, wp2, d_Kf + (size_t)(2 * hp + 1) * NFFT);

        const float D0  = D[2 * hp];
        const float D1  = D[2 * hp + 1];
        const float inv = 1.0f / (float)NFFT;
        float2* ya2 = (float2*)(y + (size_t)(2 * bp) * LSEQ * HCH) + hp;
        float2* yb2 = (float2*)(y + (size_t)(2 * bp + 1) * LSEQ * HCH) + hp;
#pragma unroll
        for (int j = 0; j < 8; j++) {
            size_t idx = (size_t)(t + 256 * j) * (HCH / 2);
            float2 la = ua2[idx];
            float2 lb = ub2[idx];
            float2 oa, ob;
            oa.x = fmaf(y0[j].x, inv, la.x * D0);
            oa.y = fmaf(v[j].x,  inv, la.y * D1);
            ob.x = fmaf(y0[j].y, inv, lb.x * D0);
            ob.y = fmaf(v[j].y,  inv, lb.y * D1);
            ya2[idx] = oa;
            yb2[idx] = ob;
        }
    }
}

// ---------------------------------------------------------------------------
extern "C" void kernel_launch(void* const* d_in, const int* in_sizes, int n_in,
                              void* d_out, int out_size) {
    const float* u   = (const float*)d_in[0];
    const float* Lr  = (const float*)d_in[1];
    const float* Li  = (const float*)d_in[2];
    const float* Pr  = (const float*)d_in[3];
    const float* Pi  = (const float*)d_in[4];
    const float* Br  = (const float*)d_in[5];
    const float* Bi  = (const float*)d_in[6];
    const float* Cr  = (const float*)d_in[7];
    const float* Ci  = (const float*)d_in[8];
    const float* ldt = (const float*)d_in[9];
    const float* D   = (const float*)d_in[10];
    float* y = (float*)d_out;

    const size_t smem = (size_t)SPAD * sizeof(float2);   // 34816 B

    zero_flags<<<1, HCH>>>();
    fused_kernel<<<HCH + (HCH / 2) * (BS / 2), 256, smem>>>(
        u, Lr, Li, Pr, Pi, Br, Bi, Cr, Ci, ldt, D, y);
}

// round 14
// speedup vs baseline: 1.3321x; 1.0110x over previous
#include <cuda_runtime.h>
#include <math.h>

#define HCH  512
#define NST  64
#define BS   8
#define LSEQ 2048
#define NFFT 4096
#define SIDX(i) ((i) + ((i) >> 4))
#define SPAD (NFFT + (NFFT >> 4))   // 4352 float2 = 34816 B

// per-channel spectrum, layout [h][j*256 + t] holding bit-rev position p=16t+j
__device__ float2 d_Kf[(size_t)HCH * NFFT];
// per-channel ready flags (reset every launch by zero_flags)
__device__ int d_flags[HCH];

// W16^m = exp(-2*pi*i*m/16), m=0..7
__constant__ float2 C16[8] = {
    { 1.0f,           0.0f},
    { 0.92387953251f, -0.38268343236f},
    { 0.70710678119f, -0.70710678119f},
    { 0.38268343236f, -0.92387953251f},
    { 0.0f,          -1.0f},
    {-0.38268343236f, -0.92387953251f},
    {-0.70710678119f, -0.70710678119f},
    {-0.92387953251f, -0.38268343236f},
};
// W8^m = exp(-2*pi*i*m/8), m=0..3
__constant__ float2 C8[4] = {
    { 1.0f,           0.0f},
    { 0.70710678119f, -0.70710678119f},
    { 0.0f,          -1.0f},
    {-0.70710678119f, -0.70710678119f},
};

typedef unsigned long long u64c;

// ---- packed f32x2 helpers (sm_100a) ----
__device__ __forceinline__ u64c pk2(float lo, float hi) {
    u64c r; asm("mov.b64 %0, {%1, %2};" : "=l"(r) : "f"(lo), "f"(hi)); return r;
}
__device__ __forceinline__ float2 unpk2(u64c v) {
    float lo, hi; asm("mov.b64 {%0, %1}, %2;" : "=f"(lo), "=f"(hi) : "l"(v));
    return make_float2(lo, hi);
}
__device__ __forceinline__ u64c ffma2_(u64c a, u64c b, u64c c) {
    u64c r; asm("fma.rn.f32x2 %0, %1, %2, %3;" : "=l"(r) : "l"(a), "l"(b), "l"(c));
    return r;
}

__device__ __forceinline__ float2 cmul(float2 a, float2 b) {
    return make_float2(fmaf(a.x, b.x, -a.y * b.y), fmaf(a.x, b.y, a.y * b.x));
}
__device__ __forceinline__ float2 cmulj(float2 a, float2 b) {   // a * conj(b)
    return make_float2(fmaf(a.x, b.x, a.y * b.y), fmaf(a.y, b.x, -a.x * b.y));
}
__device__ __forceinline__ float2 cadd(float2 a, float2 b) { return make_float2(a.x + b.x, a.y + b.y); }
__device__ __forceinline__ float2 csub(float2 a, float2 b) { return make_float2(a.x - b.x, a.y - b.y); }

__device__ __forceinline__ float2 tw4096(int j) {
    float s, c;
    sincospif((float)j * (1.0f / 2048.0f), &s, &c);
    return make_float2(c, -s);
}
__device__ __forceinline__ float2 tw2048(int j) {
    float s, c;
    sincospif((float)j * (1.0f / 1024.0f), &s, &c);
    return make_float2(c, -s);
}

// ---------------------------------------------------------------------------
// Register FFT blocks. fwd16/inv16 = 4 radix-2 DIF/DIT stages; fwd8/inv8 = 3.
// Composition of DIF passes => position p holds frequency brev(p).
// ---------------------------------------------------------------------------
__device__ __forceinline__ void fwd16(float2* v, float2 w1) {
    float2 w2 = cmul(w1, w1), w4 = cmul(w2, w2), w8 = cmul(w4, w4);
#pragma unroll
    for (int j = 0; j < 8; j++) {
        float2 tw = cmul(w1, C16[j]);
        float2 a = v[j], bb = v[j + 8];
        v[j] = cadd(a, bb);
        v[j + 8] = cmul(csub(a, bb), tw);
    }
#pragma unroll
    for (int g = 0; g < 16; g += 8)
#pragma unroll
        for (int j = 0; j < 4; j++) {
            float2 tw = cmul(w2, C16[2 * j]);
            float2 a = v[g + j], bb = v[g + j + 4];
            v[g + j] = cadd(a, bb);
            v[g + j + 4] = cmul(csub(a, bb), tw);
        }
#pragma unroll
    for (int g = 0; g < 16; g += 4)
#pragma unroll
        for (int j = 0; j < 2; j++) {
            float2 tw = cmul(w4, C16[4 * j]);
            float2 a = v[g + j], bb = v[g + j + 2];
            v[g + j] = cadd(a, bb);
            v[g + j + 2] = cmul(csub(a, bb), tw);
        }
#pragma unroll
    for (int g = 0; g < 16; g += 2) {
        float2 a = v[g], bb = v[g + 1];
        v[g] = cadd(a, bb);
        v[g + 1] = cmul(csub(a, bb), w8);
    }
}

__device__ __forceinline__ void inv16(float2* v, float2 w1) {
    float2 c1 = make_float2(w1.x, -w1.y);
    float2 c2 = cmul(c1, c1), c4 = cmul(c2, c2), c8 = cmul(c4, c4);
#pragma unroll
    for (int g = 0; g < 16; g += 2) {
        float2 tb = cmul(v[g + 1], c8);
        float2 a = v[g];
        v[g] = cadd(a, tb);
        v[g + 1] = csub(a, tb);
    }
#pragma unroll
    for (int g = 0; g < 16; g += 4)
#pragma unroll
        for (int j = 0; j < 2; j++) {
            float2 tw = cmulj(c4, C16[4 * j]);
            float2 tb = cmul(v[g + j + 2], tw);
            float2 a = v[g + j];
            v[g + j] = cadd(a, tb);
            v[g + j + 2] = csub(a, tb);
        }
#pragma unroll
    for (int g = 0; g < 16; g += 8)
#pragma unroll
        for (int j = 0; j < 4; j++) {
            float2 tw = cmulj(c2, C16[2 * j]);
            float2 tb = cmul(v[g + j + 4], tw);
            float2 a = v[g + j];
            v[g + j] = cadd(a, tb);
            v[g + j + 4] = csub(a, tb);
        }
#pragma unroll
    for (int j = 0; j < 8; j++) {
        float2 tw = cmulj(c1, C16[j]);
        float2 tb = cmul(v[j + 8], tw);
        float2 a = v[j];
        v[j] = cadd(a, tb);
        v[j + 8] = csub(a, tb);
    }
}

__device__ __forceinline__ void fwd8(float2* v, float2 w1) {
    float2 w2 = cmul(w1, w1), w4 = cmul(w2, w2);
#pragma unroll
    for (int j = 0; j < 4; j++) {
        float2 tw = cmul(w1, C8[j]);
        float2 a = v[j], bb = v[j + 4];
        v[j] = cadd(a, bb);
        v[j + 4] = cmul(csub(a, bb), tw);
    }
#pragma unroll
    for (int g = 0; g < 8; g += 4)
#pragma unroll
        for (int j = 0; j < 2; j++) {
            float2 tw = cmul(w2, C8[2 * j]);
            float2 a = v[g + j], bb = v[g + j + 2];
            v[g + j] = cadd(a, bb);
            v[g + j + 2] = cmul(csub(a, bb), tw);
        }
#pragma unroll
    for (int g = 0; g < 8; g += 2) {
        float2 a = v[g], bb = v[g + 1];
        v[g] = cadd(a, bb);
        v[g + 1] = cmul(csub(a, bb), w4);
    }
}

__device__ __forceinline__ void inv8(float2* v, float2 w1) {
    float2 c1 = make_float2(w1.x, -w1.y);
    float2 c2 = cmul(c1, c1), c4 = cmul(c2, c2);
#pragma unroll
    for (int g = 0; g < 8; g += 2) {
        float2 tb = cmul(v[g + 1], c4);
        float2 a = v[g];
        v[g] = cadd(a, tb);
        v[g + 1] = csub(a, tb);
    }
#pragma unroll
    for (int g = 0; g < 8; g += 4)
#pragma unroll
        for (int j = 0; j < 2; j++) {
            float2 tw = cmulj(c2, C8[2 * j]);
            float2 tb = cmul(v[g + j + 2], tw);
            float2 a = v[g + j];
            v[g + j] = cadd(a, tb);
            v[g + j + 2] = csub(a, tb);
        }
#pragma unroll
    for (int j = 0; j < 4; j++) {
        float2 tw = cmulj(c1, C8[j]);
        float2 tb = cmul(v[j + 4], tw);
        float2 a = v[j];
        v[j] = cadd(a, tb);
        v[j + 4] = csub(a, tb);
    }
}

// One full 4096 FFT-conv-IFFT on v[16] through smem x.
__device__ __forceinline__ void fft_conv_4096(
        float2* v, float2* x, int t, int base2,
        float2 w1, float2 wp2, const float2* __restrict__ kf) {
    fwd16(v, w1);
#pragma unroll
    for (int j = 0; j < 16; j++) x[SIDX(t + 256 * j)] = v[j];
    __syncthreads();
#pragma unroll
    for (int j = 0; j < 16; j++) v[j] = x[SIDX(base2 + 16 * j)];
    fwd16(v, wp2);
#pragma unroll
    for (int j = 0; j < 16; j++) x[SIDX(base2 + 16 * j)] = v[j];
    __syncthreads();
#pragma unroll
    for (int j = 0; j < 16; j++) v[j] = x[SIDX(16 * t + j)];
    fwd16(v, make_float2(1.f, 0.f));
#pragma unroll
    for (int j = 0; j < 16; j++) v[j] = cmul(v[j], kf[j * 256 + t]);
    inv16(v, make_float2(1.f, 0.f));
#pragma unroll
    for (int j = 0; j < 16; j++) x[SIDX(16 * t + j)] = v[j];
    __syncthreads();
#pragma unroll
    for (int j = 0; j < 16; j++) v[j] = x[SIDX(base2 + 16 * j)];
    inv16(v, wp2);
#pragma unroll
    for (int j = 0; j < 16; j++) x[SIDX(base2 + 16 * j)] = v[j];
    __syncthreads();
#pragma unroll
    for (int j = 0; j < 16; j++) v[j] = x[SIDX(t + 256 * j)];
    inv16(v, w1);
}

// ---------------------------------------------------------------------------
__global__ void zero_flags() {
    if (threadIdx.x < HCH) d_flags[threadIdx.x] = 0;
}

// ---------------------------------------------------------------------------
// Fused kernel: bids [0, HCH) = spec; bids [HCH, HCH+1024) = conv (flag-gated).
// Spec uses the zero-pad split: K^(2m) = Ã(m) (free), K^(2m+1) =
// FFT2048(K * W4096^n)(m), where Ã = Hermitian projection of at_roots.
// ---------------------------------------------------------------------------
__global__ void __launch_bounds__(256, 2) fused_kernel(
        const float* __restrict__ u,
        const float* __restrict__ Lr, const float* __restrict__ Li,
        const float* __restrict__ Pr, const float* __restrict__ Pi,
        const float* __restrict__ Br, const float* __restrict__ Bi,
        const float* __restrict__ Cr, const float* __restrict__ Ci,
        const float* __restrict__ logdt, const float* __restrict__ D,
        float* __restrict__ y) {
    extern __shared__ float2 x[];   // SPAD float2

    if (blockIdx.x < HCH) {
        // ================= SPEC branch =================
        const int h   = blockIdx.x;
        const int tid = threadIdx.x;

        __shared__ float2 lam[NST], w00[NST];
        __shared__ __align__(16) u64c WT[NST * 14];

        if (tid < NST) {
            int n = tid;
            lam[n] = make_float2(Lr[n], Li[n]);
            float2 P  = make_float2(Pr[n], Pi[n]);
            float2 Bv = make_float2(Br[n], Bi[n]);
            float2 Cc = make_float2(Cr[h * NST + n], -Ci[h * NST + n]);
            w00[n] = cmul(Cc, Bv);
        }
        __syncthreads();
        // Build packed a/b weight tables (a-lane n, b-lane m=63-n)
        if (tid < NST) {
            int n = tid, m = NST - 1 - n;
            u64c* T = &WT[n * 14];
            float2 Pn = make_float2(Pr[n], Pi[n]);
            float2 Pm = make_float2(Pr[m], Pi[m]);
            float2 Bn = make_float2(Br[n], Bi[n]);
            float2 Bm = make_float2(Br[m], Bi[m]);
            float2 Ccn = make_float2(Cr[h * NST + n], -Ci[h * NST + n]);
            float2 Ccm = make_float2(Cr[h * NST + m], -Ci[h * NST + m]);
            float2 wn, wm;
            wn = cmul(Ccn, Bn); wm = cmul(Ccm, Bm);          // w00
            T[0]  = pk2(wn.x, wm.x);  T[1]  = pk2(-wn.y, wm.y);
            T[2]  = pk2(wn.x, -wm.x); T[3]  = pk2(wn.y, wm.y);
            wn = cmul(Ccn, Pn); wm = cmul(Ccm, Pm);          // w01
            T[4]  = pk2(wn.x, wm.x);  T[5]  = pk2(-wn.y, wm.y);
            T[6]  = pk2(wn.x, -wm.x); T[7]  = pk2(wn.y, wm.y);
            float2 Qcn = make_float2(Pn.x, -Pn.y);
            float2 Qcm = make_float2(Pm.x, -Pm.y);
            wn = cmul(Qcn, Bn); wm = cmul(Qcm, Bm);          // w10
            T[8]  = pk2(wn.x, wm.x);  T[9]  = pk2(-wn.y, wm.y);
            T[10] = pk2(wn.x, -wm.x); T[11] = pk2(wn.y, wm.y);
            float w11n = Pn.x * Pn.x + Pn.y * Pn.y;
            float w11m = Pm.x * Pm.x + Pm.y * Pm.y;
            T[12] = pk2(w11n, w11m);
            T[13] = pk2(w11n, -w11m);
        }
        __syncthreads();

        const float dt = expf(logdt[h]);
        const float g0 = 2.0f / dt;

        // ---- Ã(l) = (A(l)+conj(A(2048-l)))/2, stored at brev11 positions ----
        for (int l = tid; l < 1024; l += blockDim.x) {
            float ss, cc;
            sincospif((float)l * (1.0f / 1024.0f), &ss, &cc);
            float2 om = make_float2(cc, -ss);
            float2 den = make_float2(1.f + om.x, om.y);
            float2 num = make_float2(1.f - om.x, -om.y);
            float idl  = __fdividef(1.f, den.x * den.x + den.y * den.y);
            float2 c2  = make_float2(2.f * den.x * idl, -2.f * den.y * idl);
            float2 gf  = cmul(num, make_float2(den.x, -den.y));
            float2 g   = make_float2(g0 * gf.x * idl, g0 * gf.y * idl);

            u64c K00R = 0, K00I = 0, K01R = 0, K01I = 0;
            u64c K10R = 0, K10I = 0, K11R = 0, K11I = 0;
#pragma unroll 4
            for (int n = 0; n < NST; n++) {
                float2 L = lam[n];
                float dx = g.x - L.x;
                float dy = g.y - L.y;
                float iv = __fdividef(1.f, fmaf(dx, dx, dy * dy));
                float rx = dx * iv;
                float ry = -dy * iv;
                u64c RX = pk2(rx, rx);
                u64c RY = pk2(ry, ry);
                const u64c* T = &WT[n * 14];
                ulonglong2 t0 = *(const ulonglong2*)(T + 0);
                ulonglong2 t1 = *(const ulonglong2*)(T + 2);
                ulonglong2 t2 = *(const ulonglong2*)(T + 4);
                ulonglong2 t3 = *(const ulonglong2*)(T + 6);
                ulonglong2 t4 = *(const ulonglong2*)(T + 8);
                ulonglong2 t5 = *(const ulonglong2*)(T + 10);
                ulonglong2 t6 = *(const ulonglong2*)(T + 12);
                K00R = ffma2_(t0.x, RX, K00R);  K00R = ffma2_(t0.y, RY, K00R);
                K00I = ffma2_(t1.x, RY, K00I);  K00I = ffma2_(t1.y, RX, K00I);
                K01R = ffma2_(t2.x, RX, K01R);  K01R = ffma2_(t2.y, RY, K01R);
                K01I = ffma2_(t3.x, RY, K01I);  K01I = ffma2_(t3.y, RX, K01I);
                K10R = ffma2_(t4.x, RX, K10R);  K10R = ffma2_(t4.y, RY, K10R);
                K10I = ffma2_(t5.x, RY, K10I);  K10I = ffma2_(t5.y, RX, K10I);
                K11R = ffma2_(t6.x, RX, K11R);
                K11I = ffma2_(t6.y, RY, K11I);
            }
            float2 r00 = unpk2(K00R), i00 = unpk2(K00I);
            float2 r01 = unpk2(K01R), i01 = unpk2(K01I);
            float2 r10 = unpk2(K10R), i10 = unpk2(K10I);
            float2 r11 = unpk2(K11R), i11 = unpk2(K11I);
            float2 a00 = make_float2(r00.x, i00.x), b00 = make_float2(r00.y, i00.y);
            float2 a01 = make_float2(r01.x, i01.x), b01 = make_float2(r01.y, i01.y);
            float2 a10 = make_float2(r10.x, i10.x), b10 = make_float2(r10.y, i10.y);
            float2 a11 = make_float2(r11.x, i11.x), b11 = make_float2(r11.y, i11.y);

            float2 Aa;
            {   // A[l]
                float2 onep = make_float2(1.f + a11.x, a11.y);
                float  ip   = __fdividef(1.f, onep.x * onep.x + onep.y * onep.y);
                float2 invd = make_float2(onep.x * ip, -onep.y * ip);
                float2 t2   = cmul(cmul(a01, a10), invd);
                Aa = cmul(c2, csub(a00, t2));
            }
            if (l != 0) {
                float2 Ab;   // A[2048-l]
                float2 c2c  = make_float2(c2.x, -c2.y);
                float2 onep = make_float2(1.f + b11.x, b11.y);
                float  ip   = __fdividef(1.f, onep.x * onep.x + onep.y * onep.y);
                float2 invd = make_float2(onep.x * ip, -onep.y * ip);
                float2 t2   = cmul(cmul(b01, b10), invd);
                Ab = cmul(c2c, csub(b00, t2));
                // Hermitian projection: Ã(l), Ã(2048-l)=conj(Ã(l))
                float2 At = make_float2(0.5f * (Aa.x + Ab.x), 0.5f * (Aa.y - Ab.y));
                int rl  = __brev(l) >> 21;
                int rl2 = __brev(2048 - l) >> 21;
                x[SIDX(rl)]  = At;
                x[SIDX(rl2)] = make_float2(At.x, -At.y);
            } else {
                // Ã(0) = Re(A(0)); brev11(0) = 0
                x[SIDX(0)] = make_float2(Aa.x, 0.f);
            }
        }
        if (tid == 0) {
            // l = 1024: omega = -1 limit; Ã(1024) = Re(A(1024)); brev11(1024)=1
            float2 s = make_float2(0.f, 0.f);
            for (int n = 0; n < NST; n++) s = cadd(s, w00[n]);
            x[SIDX(1)] = make_float2(0.5f * dt * s.x, 0.f);
        }
        __syncthreads();

        float2* kf = d_Kf + (size_t)h * NFFT;

        // ---- EVEN half of K^: kf[j*256+t] = Ã at position p=16t+j (t<128) ----
#pragma unroll
        for (int s = 0; s < 8; s++) {
            int e  = tid + 256 * s;          // 0..2047
            int j  = e >> 7;                 // 0..15
            int tt = e & 127;                // 0..127
            kf[j * 256 + tt] = x[SIDX(16 * tt + j)];
        }
        __syncthreads();

        // ---- IFFT-2048 (inv8 {8t+j}, inv16 {baseB+8j}, inv16 {t+128j}) ----
        {
            float2 v8[8];
#pragma unroll
            for (int j = 0; j < 8; j++) v8[j] = x[SIDX(8 * tid + j)];
            inv8(v8, make_float2(1.f, 0.f));
#pragma unroll
            for (int j = 0; j < 8; j++) x[SIDX(8 * tid + j)] = v8[j];
        }
        __syncthreads();
        {
            float2 v[16];
            if (tid < 128) {
                int baseB = ((tid >> 3) << 7) + (tid & 7);
#pragma unroll
                for (int j = 0; j < 16; j++) v[j] = x[SIDX(baseB + 8 * j)];
                inv16(v, tw2048(16 * (tid & 7)));
#pragma unroll
                for (int j = 0; j < 16; j++) x[SIDX(baseB + 8 * j)] = v[j];
            }
            __syncthreads();
            if (tid < 128) {
#pragma unroll
                for (int j = 0; j < 16; j++) v[j] = x[SIDX(tid + 128 * j)];
                inv16(v, tw2048(tid));
                // scale + realify + modulate by W4096^n (n = tid + 128*j);
                // same per-thread addresses (no barrier needed)
                const float  sc   = 1.0f / 2048.0f;
                const float2 C128 = make_float2(0.98078528040323044913f,
                                                -0.19509032201612826785f); // W4096^128
                float2 wn = tw4096(tid);
#pragma unroll
                for (int j = 0; j < 16; j++) {
                    float kk = v[j].x * sc;
                    x[SIDX(tid + 128 * j)] = make_float2(kk * wn.x, kk * wn.y);
                    wn = cmul(wn, C128);
                }
            }
        }
        __syncthreads();

        // ---- forward FFT-2048 on modulated K (natural -> brev11 positions) ----
        {
            float2 v[16];
            if (tid < 128) {
#pragma unroll
                for (int j = 0; j < 16; j++) v[j] = x[SIDX(tid + 128 * j)];
                fwd16(v, tw2048(tid));
#pragma unroll
                for (int j = 0; j < 16; j++) x[SIDX(tid + 128 * j)] = v[j];
            }
            __syncthreads();
            if (tid < 128) {
                int baseB = ((tid >> 3) << 7) + (tid & 7);
#pragma unroll
                for (int j = 0; j < 16; j++) v[j] = x[SIDX(baseB + 8 * j)];
                fwd16(v, tw2048((tid & 7) << 4));
#pragma unroll
                for (int j = 0; j < 16; j++) x[SIDX(baseB + 8 * j)] = v[j];
            }
            __syncthreads();
        }
        {
            float2 v8[8];
#pragma unroll
            for (int j = 0; j < 8; j++) v8[j] = x[SIDX(8 * tid + j)];
            fwd8(v8, make_float2(1.f, 0.f));
            // ---- ODD half of K^: position q=8*tid+j -> kf[(q&15)*256+128+(q>>4)]
#pragma unroll
            for (int j = 0; j < 8; j++) {
                int q = 8 * tid + j;
                kf[(q & 15) * 256 + 128 + (q >> 4)] = v8[j];
            }
        }

        // release
        __syncthreads();
        if (tid == 0) {
            __threadfence();
            atomicExch(&d_flags[h], 1);
        }
    } else {
        // ================= CONV branch =================
        const int i  = blockIdx.x - HCH;
        const int hp = i & (HCH / 2 - 1);      // 0..255
        const int bp = i >> 8;                 // 0..3
        const int t  = threadIdx.x;

        if (t == 0) {
            while (atomicAdd(&d_flags[2 * hp], 0) == 0) __nanosleep(200);
            while (atomicAdd(&d_flags[2 * hp + 1], 0) == 0) __nanosleep(200);
            __threadfence();
        }
        __syncthreads();

        const float2* ua2 = (const float2*)(u + (size_t)(2 * bp) * LSEQ * HCH) + hp;
        const float2* ub2 = (const float2*)(u + (size_t)(2 * bp + 1) * LSEQ * HCH) + hp;

        float2 v[16], z1[8], y0[8];
#pragma unroll
        for (int j = 0; j < 8; j++) {
            size_t idx = (size_t)(t + 256 * j) * (HCH / 2);
            float2 la = ua2[idx];
            float2 lb = ub2[idx];
            v[j]  = make_float2(la.x, lb.x);   // channel 2hp:   b0 + i*b1
            z1[j] = make_float2(la.y, lb.y);   // channel 2hp+1: b0 + i*b1
        }
#pragma unroll
        for (int j = 8; j < 16; j++) v[j] = make_float2(0.f, 0.f);

        const float2 w1  = tw4096(t);
        const float2 wp2 = tw4096((t & 15) << 4);
        const int base2  = ((t >> 4) << 8) + (t & 15);

        fft_conv_4096(v, x, t, base2, w1, wp2, d_Kf + (size_t)(2 * hp) * NFFT);
#pragma unroll
        for (int j = 0; j < 8; j++) y0[j] = v[j];

#pragma unroll
        for (int j = 0; j < 8; j++) v[j] = z1[j];
#pragma unroll
        for (int j = 8; j < 16; j++) v[j] = make_float2(0.f, 0.f);
        fft_conv_4096(v, x, t, base2, w1, wp2, d_Kf + (size_t)(2 * hp + 1) * NFFT);

        const float D0  = D[2 * hp];
        const float D1  = D[2 * hp + 1];
        const float inv = 1.0f / (float)NFFT;
        float2* ya2 = (float2*)(y + (size_t)(2 * bp) * LSEQ * HCH) + hp;
        float2* yb2 = (float2*)(y + (size_t)(2 * bp + 1) * LSEQ * HCH) + hp;
#pragma unroll
        for (int j = 0; j < 8; j++) {
            size_t idx = (size_t)(t + 256 * j) * (HCH / 2);
            float2 la = ua2[idx];
            float2 lb = ub2[idx];
            float2 oa, ob;
            oa.x = fmaf(y0[j].x, inv, la.x * D0);
            oa.y = fmaf(v[j].x,  inv, la.y * D1);
            ob.x = fmaf(y0[j].y, inv, lb.x * D0);
            ob.y = fmaf(v[j].y,  inv, lb.y * D1);
            ya2[idx] = oa;
            yb2[idx] = ob;
        }
    }
}

// ---------------------------------------------------------------------------
extern "C" void kernel_launch(void* const* d_in, const int* in_sizes, int n_in,
                              void* d_out, int out_size) {
    const float* u   = (const float*)d_in[0];
    const float* Lr  = (const float*)d_in[1];
    const float* Li  = (const float*)d_in[2];
    const float* Pr  = (const float*)d_in[3];
    const float* Pi  = (const float*)d_in[4];
    const float* Br  = (const float*)d_in[5];
    const float* Bi  = (const float*)d_in[6];
    const float* Cr  = (const float*)d_in[7];
    const float* Ci  = (const float*)d_in[8];
    const float* ldt = (const float*)d_in[9];
    const float* D   = (const float*)d_in[10];
    float* y = (float*)d_out;

    const size_t smem = (size_t)SPAD * sizeof(float2);   // 34816 B

    zero_flags<<<1, HCH>>>();
    fused_kernel<<<HCH + (HCH / 2) * (BS / 2), 256, smem>>>(
        u, Lr, Li, Pr, Pi, Br, Bi, Cr, Ci, ldt, D, y);
}

// round 15
// speedup vs baseline: 1.3323x; 1.0002x over previous
#include <cuda_runtime.h>
#include <math.h>

#define HCH  512
#define NST  64
#define BS   8
#define LSEQ 2048
#define NFFT 4096
#define SIDX(i) ((i) + ((i) >> 4))
#define SPAD (NFFT + (NFFT >> 4))   // 4352 float2 = 34816 B

// per-channel spectrum, layout [h][j*256 + t] holding bit-rev position p=16t+j
__device__ float2 d_Kf[(size_t)HCH * NFFT];
// per-channel ready flags (reset every launch by zero_flags)
__device__ int d_flags[HCH];

// W16^m = exp(-2*pi*i*m/16), m=0..7
__constant__ float2 C16[8] = {
    { 1.0f,           0.0f},
    { 0.92387953251f, -0.38268343236f},
    { 0.70710678119f, -0.70710678119f},
    { 0.38268343236f, -0.92387953251f},
    { 0.0f,          -1.0f},
    {-0.38268343236f, -0.92387953251f},
    {-0.70710678119f, -0.70710678119f},
    {-0.92387953251f, -0.38268343236f},
};
// W8^m = exp(-2*pi*i*m/8), m=0..3
__constant__ float2 C8[4] = {
    { 1.0f,           0.0f},
    { 0.70710678119f, -0.70710678119f},
    { 0.0f,          -1.0f},
    {-0.70710678119f, -0.70710678119f},
};

typedef unsigned long long u64c;

// ---- packed f32x2 helpers (sm_100a) ----
__device__ __forceinline__ u64c pk2(float lo, float hi) {
    u64c r; asm("mov.b64 %0, {%1, %2};" : "=l"(r) : "f"(lo), "f"(hi)); return r;
}
__device__ __forceinline__ float2 unpk2(u64c v) {
    float lo, hi; asm("mov.b64 {%0, %1}, %2;" : "=f"(lo), "=f"(hi) : "l"(v));
    return make_float2(lo, hi);
}
__device__ __forceinline__ u64c ffma2_(u64c a, u64c b, u64c c) {
    u64c r; asm("fma.rn.f32x2 %0, %1, %2, %3;" : "=l"(r) : "l"(a), "l"(b), "l"(c));
    return r;
}
__device__ __forceinline__ u64c fadd2_(u64c a, u64c b) {
    u64c r; asm("add.rn.f32x2 %0, %1, %2;" : "=l"(r) : "l"(a), "l"(b));
    return r;
}

__device__ __forceinline__ float2 cmul(float2 a, float2 b) {
    return make_float2(fmaf(a.x, b.x, -a.y * b.y), fmaf(a.x, b.y, a.y * b.x));
}
__device__ __forceinline__ float2 cmulj(float2 a, float2 b) {   // a * conj(b)
    return make_float2(fmaf(a.x, b.x, a.y * b.y), fmaf(a.y, b.x, -a.x * b.y));
}
__device__ __forceinline__ float2 cadd(float2 a, float2 b) { return make_float2(a.x + b.x, a.y + b.y); }
__device__ __forceinline__ float2 csub(float2 a, float2 b) { return make_float2(a.x - b.x, a.y - b.y); }

__device__ __forceinline__ float2 tw4096(int j) {
    float s, c;
    sincospif((float)j * (1.0f / 2048.0f), &s, &c);
    return make_float2(c, -s);
}
__device__ __forceinline__ float2 tw2048(int j) {
    float s, c;
    sincospif((float)j * (1.0f / 1024.0f), &s, &c);
    return make_float2(c, -s);
}

// ---------------------------------------------------------------------------
// Register FFT blocks. fwd16/inv16 = 4 radix-2 DIF/DIT stages; fwd8/inv8 = 3.
// Composition of DIF passes => position p holds frequency brev(p).
// ---------------------------------------------------------------------------
__device__ __forceinline__ void fwd16(float2* v, float2 w1) {
    float2 w2 = cmul(w1, w1), w4 = cmul(w2, w2), w8 = cmul(w4, w4);
#pragma unroll
    for (int j = 0; j < 8; j++) {
        float2 tw = cmul(w1, C16[j]);
        float2 a = v[j], bb = v[j + 8];
        v[j] = cadd(a, bb);
        v[j + 8] = cmul(csub(a, bb), tw);
    }
#pragma unroll
    for (int g = 0; g < 16; g += 8)
#pragma unroll
        for (int j = 0; j < 4; j++) {
            float2 tw = cmul(w2, C16[2 * j]);
            float2 a = v[g + j], bb = v[g + j + 4];
            v[g + j] = cadd(a, bb);
            v[g + j + 4] = cmul(csub(a, bb), tw);
        }
#pragma unroll
    for (int g = 0; g < 16; g += 4)
#pragma unroll
        for (int j = 0; j < 2; j++) {
            float2 tw = cmul(w4, C16[4 * j]);
            float2 a = v[g + j], bb = v[g + j + 2];
            v[g + j] = cadd(a, bb);
            v[g + j + 2] = cmul(csub(a, bb), tw);
        }
#pragma unroll
    for (int g = 0; g < 16; g += 2) {
        float2 a = v[g], bb = v[g + 1];
        v[g] = cadd(a, bb);
        v[g + 1] = cmul(csub(a, bb), w8);
    }
}

// Zero-padded variant: v[8..15] implicitly zero on entry (not read).
__device__ __forceinline__ void fwd16z(float2* v, float2 w1) {
    float2 w2 = cmul(w1, w1), w4 = cmul(w2, w2), w8 = cmul(w4, w4);
#pragma unroll
    for (int j = 0; j < 8; j++) {
        float2 tw = cmul(w1, C16[j]);
        v[j + 8] = cmul(v[j], tw);     // a + 0, (a - 0)*tw
    }
#pragma unroll
    for (int g = 0; g < 16; g += 8)
#pragma unroll
        for (int j = 0; j < 4; j++) {
            float2 tw = cmul(w2, C16[2 * j]);
            float2 a = v[g + j], bb = v[g + j + 4];
            v[g + j] = cadd(a, bb);
            v[g + j + 4] = cmul(csub(a, bb), tw);
        }
#pragma unroll
    for (int g = 0; g < 16; g += 4)
#pragma unroll
        for (int j = 0; j < 2; j++) {
            float2 tw = cmul(w4, C16[4 * j]);
            float2 a = v[g + j], bb = v[g + j + 2];
            v[g + j] = cadd(a, bb);
            v[g + j + 2] = cmul(csub(a, bb), tw);
        }
#pragma unroll
    for (int g = 0; g < 16; g += 2) {
        float2 a = v[g], bb = v[g + 1];
        v[g] = cadd(a, bb);
        v[g + 1] = cmul(csub(a, bb), w8);
    }
}

__device__ __forceinline__ void inv16(float2* v, float2 w1) {
    float2 c1 = make_float2(w1.x, -w1.y);
    float2 c2 = cmul(c1, c1), c4 = cmul(c2, c2), c8 = cmul(c4, c4);
#pragma unroll
    for (int g = 0; g < 16; g += 2) {
        float2 tb = cmul(v[g + 1], c8);
        float2 a = v[g];
        v[g] = cadd(a, tb);
        v[g + 1] = csub(a, tb);
    }
#pragma unroll
    for (int g = 0; g < 16; g += 4)
#pragma unroll
        for (int j = 0; j < 2; j++) {
            float2 tw = cmulj(c4, C16[4 * j]);
            float2 tb = cmul(v[g + j + 2], tw);
            float2 a = v[g + j];
            v[g + j] = cadd(a, tb);
            v[g + j + 2] = csub(a, tb);
        }
#pragma unroll
    for (int g = 0; g < 16; g += 8)
#pragma unroll
        for (int j = 0; j < 4; j++) {
            float2 tw = cmulj(c2, C16[2 * j]);
            float2 tb = cmul(v[g + j + 4], tw);
            float2 a = v[g + j];
            v[g + j] = cadd(a, tb);
            v[g + j + 4] = csub(a, tb);
        }
#pragma unroll
    for (int j = 0; j < 8; j++) {
        float2 tw = cmulj(c1, C16[j]);
        float2 tb = cmul(v[j + 8], tw);
        float2 a = v[j];
        v[j] = cadd(a, tb);
        v[j + 8] = csub(a, tb);
    }
}

__device__ __forceinline__ void fwd8(float2* v, float2 w1) {
    float2 w2 = cmul(w1, w1), w4 = cmul(w2, w2);
#pragma unroll
    for (int j = 0; j < 4; j++) {
        float2 tw = cmul(w1, C8[j]);
        float2 a = v[j], bb = v[j + 4];
        v[j] = cadd(a, bb);
        v[j + 4] = cmul(csub(a, bb), tw);
    }
#pragma unroll
    for (int g = 0; g < 8; g += 4)
#pragma unroll
        for (int j = 0; j < 2; j++) {
            float2 tw = cmul(w2, C8[2 * j]);
            float2 a = v[g + j], bb = v[g + j + 2];
            v[g + j] = cadd(a, bb);
            v[g + j + 2] = cmul(csub(a, bb), tw);
        }
#pragma unroll
    for (int g = 0; g < 8; g += 2) {
        float2 a = v[g], bb = v[g + 1];
        v[g] = cadd(a, bb);
        v[g + 1] = cmul(csub(a, bb), w4);
    }
}

__device__ __forceinline__ void inv8(float2* v, float2 w1) {
    float2 c1 = make_float2(w1.x, -w1.y);
    float2 c2 = cmul(c1, c1), c4 = cmul(c2, c2);
#pragma unroll
    for (int g = 0; g < 8; g += 2) {
        float2 tb = cmul(v[g + 1], c4);
        float2 a = v[g];
        v[g] = cadd(a, tb);
        v[g + 1] = csub(a, tb);
    }
#pragma unroll
    for (int g = 0; g < 8; g += 4)
#pragma unroll
        for (int j = 0; j < 2; j++) {
            float2 tw = cmulj(c2, C8[2 * j]);
            float2 tb = cmul(v[g + j + 2], tw);
            float2 a = v[g + j];
            v[g + j] = cadd(a, tb);
            v[g + j + 2] = csub(a, tb);
        }
#pragma unroll
    for (int j = 0; j < 4; j++) {
        float2 tw = cmulj(c1, C8[j]);
        float2 tb = cmul(v[j + 4], tw);
        float2 a = v[j];
        v[j] = cadd(a, tb);
        v[j + 4] = csub(a, tb);
    }
}

// One full 4096 FFT-conv-IFFT on v[16] through smem x.
// Input: v[0..7] data, v[8..15] implicitly zero (zero-padded signal).
__device__ __forceinline__ void fft_conv_4096(
        float2* v, float2* x, int t, int base2,
        float2 w1, float2 wp2, const float2* __restrict__ kf) {
    fwd16z(v, w1);
#pragma unroll
    for (int j = 0; j < 16; j++) x[SIDX(t + 256 * j)] = v[j];
    __syncthreads();
#pragma unroll
    for (int j = 0; j < 16; j++) v[j] = x[SIDX(base2 + 16 * j)];
    fwd16(v, wp2);
#pragma unroll
    for (int j = 0; j < 16; j++) x[SIDX(base2 + 16 * j)] = v[j];
    __syncthreads();
#pragma unroll
    for (int j = 0; j < 16; j++) v[j] = x[SIDX(16 * t + j)];
    fwd16(v, make_float2(1.f, 0.f));
#pragma unroll
    for (int j = 0; j < 16; j++) v[j] = cmul(v[j], kf[j * 256 + t]);
    inv16(v, make_float2(1.f, 0.f));
#pragma unroll
    for (int j = 0; j < 16; j++) x[SIDX(16 * t + j)] = v[j];
    __syncthreads();
#pragma unroll
    for (int j = 0; j < 16; j++) v[j] = x[SIDX(base2 + 16 * j)];
    inv16(v, wp2);
#pragma unroll
    for (int j = 0; j < 16; j++) x[SIDX(base2 + 16 * j)] = v[j];
    __syncthreads();
#pragma unroll
    for (int j = 0; j < 16; j++) v[j] = x[SIDX(t + 256 * j)];
    inv16(v, w1);
}

// ---------------------------------------------------------------------------
__global__ void zero_flags() {
    if (threadIdx.x < HCH) d_flags[threadIdx.x] = 0;
}

// ---------------------------------------------------------------------------
// Fused kernel: bids [0, HCH) = spec; bids [HCH, HCH+1024) = conv (flag-gated).
// Spec: zero-pad split (even half of K^ = Hermitian-projected at_roots; odd
// half = modulated 2048-FFT). Cauchy loop: split accumulator chains for ILP.
// ---------------------------------------------------------------------------
__global__ void __launch_bounds__(256, 2) fused_kernel(
        const float* __restrict__ u,
        const float* __restrict__ Lr, const float* __restrict__ Li,
        const float* __restrict__ Pr, const float* __restrict__ Pi,
        const float* __restrict__ Br, const float* __restrict__ Bi,
        const float* __restrict__ Cr, const float* __restrict__ Ci,
        const float* __restrict__ logdt, const float* __restrict__ D,
        float* __restrict__ y) {
    extern __shared__ float2 x[];   // SPAD float2

    if (blockIdx.x < HCH) {
        // ================= SPEC branch =================
        const int h   = blockIdx.x;
        const int tid = threadIdx.x;

        __shared__ float2 lam[NST], w00[NST];
        __shared__ __align__(16) u64c WT[NST * 14];

        if (tid < NST) {
            int n = tid;
            lam[n] = make_float2(Lr[n], Li[n]);
            float2 P  = make_float2(Pr[n], Pi[n]);
            float2 Bv = make_float2(Br[n], Bi[n]);
            float2 Cc = make_float2(Cr[h * NST + n], -Ci[h * NST + n]);
            w00[n] = cmul(Cc, Bv);
        }
        __syncthreads();
        // Build packed a/b weight tables (a-lane n, b-lane m=63-n)
        if (tid < NST) {
            int n = tid, m = NST - 1 - n;
            u64c* T = &WT[n * 14];
            float2 Pn = make_float2(Pr[n], Pi[n]);
            float2 Pm = make_float2(Pr[m], Pi[m]);
            float2 Bn = make_float2(Br[n], Bi[n]);
            float2 Bm = make_float2(Br[m], Bi[m]);
            float2 Ccn = make_float2(Cr[h * NST + n], -Ci[h * NST + n]);
            float2 Ccm = make_float2(Cr[h * NST + m], -Ci[h * NST + m]);
            float2 wn, wm;
            wn = cmul(Ccn, Bn); wm = cmul(Ccm, Bm);          // w00
            T[0]  = pk2(wn.x, wm.x);  T[1]  = pk2(-wn.y, wm.y);
            T[2]  = pk2(wn.x, -wm.x); T[3]  = pk2(wn.y, wm.y);
            wn = cmul(Ccn, Pn); wm = cmul(Ccm, Pm);          // w01
            T[4]  = pk2(wn.x, wm.x);  T[5]  = pk2(-wn.y, wm.y);
            T[6]  = pk2(wn.x, -wm.x); T[7]  = pk2(wn.y, wm.y);
            float2 Qcn = make_float2(Pn.x, -Pn.y);
            float2 Qcm = make_float2(Pm.x, -Pm.y);
            wn = cmul(Qcn, Bn); wm = cmul(Qcm, Bm);          // w10
            T[8]  = pk2(wn.x, wm.x);  T[9]  = pk2(-wn.y, wm.y);
            T[10] = pk2(wn.x, -wm.x); T[11] = pk2(wn.y, wm.y);
            float w11n = Pn.x * Pn.x + Pn.y * Pn.y;
            float w11m = Pm.x * Pm.x + Pm.y * Pm.y;
            T[12] = pk2(w11n, w11m);
            T[13] = pk2(w11n, -w11m);
        }
        __syncthreads();

        const float dt = expf(logdt[h]);
        const float g0 = 2.0f / dt;

        // ---- Ã(l) = (A(l)+conj(A(2048-l)))/2, stored at brev11 positions ----
        for (int l = tid; l < 1024; l += blockDim.x) {
            float ss, cc;
            sincospif((float)l * (1.0f / 1024.0f), &ss, &cc);
            float2 om = make_float2(cc, -ss);
            float2 den = make_float2(1.f + om.x, om.y);
            float2 num = make_float2(1.f - om.x, -om.y);
            float idl  = __fdividef(1.f, den.x * den.x + den.y * den.y);
            float2 c2  = make_float2(2.f * den.x * idl, -2.f * den.y * idl);
            float2 gf  = cmul(num, make_float2(den.x, -den.y));
            float2 g   = make_float2(g0 * gf.x * idl, g0 * gf.y * idl);

            // split accumulator chains: X-path and Y-path independent
            u64c K00Ra = 0, K00Rb = 0, K00Ia = 0, K00Ib = 0;
            u64c K01Ra = 0, K01Rb = 0, K01Ia = 0, K01Ib = 0;
            u64c K10Ra = 0, K10Rb = 0, K10Ia = 0, K10Ib = 0;
            u64c K11R = 0, K11I = 0;
#pragma unroll 4
            for (int n = 0; n < NST; n++) {
                float2 L = lam[n];
                float dx = g.x - L.x;
                float dy = g.y - L.y;
                float iv = __fdividef(1.f, fmaf(dx, dx, dy * dy));
                float rx = dx * iv;
                float ry = -dy * iv;
                u64c RX = pk2(rx, rx);
                u64c RY = pk2(ry, ry);
                const u64c* T = &WT[n * 14];
                ulonglong2 t0 = *(const ulonglong2*)(T + 0);
                ulonglong2 t1 = *(const ulonglong2*)(T + 2);
                ulonglong2 t2 = *(const ulonglong2*)(T + 4);
                ulonglong2 t3 = *(const ulonglong2*)(T + 6);
                ulonglong2 t4 = *(const ulonglong2*)(T + 8);
                ulonglong2 t5 = *(const ulonglong2*)(T + 10);
                ulonglong2 t6 = *(const ulonglong2*)(T + 12);
                K00Ra = ffma2_(t0.x, RX, K00Ra);  K00Rb = ffma2_(t0.y, RY, K00Rb);
                K00Ia = ffma2_(t1.x, RY, K00Ia);  K00Ib = ffma2_(t1.y, RX, K00Ib);
                K01Ra = ffma2_(t2.x, RX, K01Ra);  K01Rb = ffma2_(t2.y, RY, K01Rb);
                K01Ia = ffma2_(t3.x, RY, K01Ia);  K01Ib = ffma2_(t3.y, RX, K01Ib);
                K10Ra = ffma2_(t4.x, RX, K10Ra);  K10Rb = ffma2_(t4.y, RY, K10Rb);
                K10Ia = ffma2_(t5.x, RY, K10Ia);  K10Ib = ffma2_(t5.y, RX, K10Ib);
                K11R = ffma2_(t6.x, RX, K11R);
                K11I = ffma2_(t6.y, RY, K11I);
            }
            float2 r00 = unpk2(fadd2_(K00Ra, K00Rb)), i00 = unpk2(fadd2_(K00Ia, K00Ib));
            float2 r01 = unpk2(fadd2_(K01Ra, K01Rb)), i01 = unpk2(fadd2_(K01Ia, K01Ib));
            float2 r10 = unpk2(fadd2_(K10Ra, K10Rb)), i10 = unpk2(fadd2_(K10Ia, K10Ib));
            float2 r11 = unpk2(K11R), i11 = unpk2(K11I);
            float2 a00 = make_float2(r00.x, i00.x), b00 = make_float2(r00.y, i00.y);
            float2 a01 = make_float2(r01.x, i01.x), b01 = make_float2(r01.y, i01.y);
            float2 a10 = make_float2(r10.x, i10.x), b10 = make_float2(r10.y, i10.y);
            float2 a11 = make_float2(r11.x, i11.x), b11 = make_float2(r11.y, i11.y);

            float2 Aa;
            {   // A[l]
                float2 onep = make_float2(1.f + a11.x, a11.y);
                float  ip   = __fdividef(1.f, onep.x * onep.x + onep.y * onep.y);
                float2 invd = make_float2(onep.x * ip, -onep.y * ip);
                float2 t2   = cmul(cmul(a01, a10), invd);
                Aa = cmul(c2, csub(a00, t2));
            }
            if (l != 0) {
                float2 Ab;   // A[2048-l]
                float2 c2c  = make_float2(c2.x, -c2.y);
                float2 onep = make_float2(1.f + b11.x, b11.y);
                float  ip   = __fdividef(1.f, onep.x * onep.x + onep.y * onep.y);
                float2 invd = make_float2(onep.x * ip, -onep.y * ip);
                float2 t2   = cmul(cmul(b01, b10), invd);
                Ab = cmul(c2c, csub(b00, t2));
                // Hermitian projection: Ã(l), Ã(2048-l)=conj(Ã(l))
                float2 At = make_float2(0.5f * (Aa.x + Ab.x), 0.5f * (Aa.y - Ab.y));
                int rl  = __brev(l) >> 21;
                int rl2 = __brev(2048 - l) >> 21;
                x[SIDX(rl)]  = At;
                x[SIDX(rl2)] = make_float2(At.x, -At.y);
            } else {
                x[SIDX(0)] = make_float2(Aa.x, 0.f);
            }
        }
        if (tid == 0) {
            // l = 1024: omega = -1 limit; Ã(1024) = Re(A(1024)); brev11(1024)=1
            float2 s = make_float2(0.f, 0.f);
            for (int n = 0; n < NST; n++) s = cadd(s, w00[n]);
            x[SIDX(1)] = make_float2(0.5f * dt * s.x, 0.f);
        }
        __syncthreads();

        float2* kf = d_Kf + (size_t)h * NFFT;

        // ---- EVEN half of K^: kf[j*256+t] = Ã at position p=16t+j (t<128) ----
#pragma unroll
        for (int s = 0; s < 8; s++) {
            int e  = tid + 256 * s;          // 0..2047
            int j  = e >> 7;                 // 0..15
            int tt = e & 127;                // 0..127
            kf[j * 256 + tt] = x[SIDX(16 * tt + j)];
        }
        __syncthreads();

        // ---- IFFT-2048 (inv8 {8t+j}, inv16 {baseB+8j}, inv16 {t+128j}) ----
        {
            float2 v8[8];
#pragma unroll
            for (int j = 0; j < 8; j++) v8[j] = x[SIDX(8 * tid + j)];
            inv8(v8, make_float2(1.f, 0.f));
#pragma unroll
            for (int j = 0; j < 8; j++) x[SIDX(8 * tid + j)] = v8[j];
        }
        __syncthreads();
        {
            float2 v[16];
            if (tid < 128) {
                int baseB = ((tid >> 3) << 7) + (tid & 7);
#pragma unroll
                for (int j = 0; j < 16; j++) v[j] = x[SIDX(baseB + 8 * j)];
                inv16(v, tw2048(16 * (tid & 7)));
#pragma unroll
                for (int j = 0; j < 16; j++) x[SIDX(baseB + 8 * j)] = v[j];
            }
            __syncthreads();
            if (tid < 128) {
#pragma unroll
                for (int j = 0; j < 16; j++) v[j] = x[SIDX(tid + 128 * j)];
                inv16(v, tw2048(tid));
                // scale + realify + modulate by W4096^n (n = tid + 128*j)
                const float  sc   = 1.0f / 2048.0f;
                const float2 C128 = make_float2(0.98078528040323044913f,
                                                -0.19509032201612826785f); // W4096^128
                float2 wn = tw4096(tid);
#pragma unroll
                for (int j = 0; j < 16; j++) {
                    float kk = v[j].x * sc;
                    x[SIDX(tid + 128 * j)] = make_float2(kk * wn.x, kk * wn.y);
                    wn = cmul(wn, C128);
                }
            }
        }
        __syncthreads();

        // ---- forward FFT-2048 on modulated K (natural -> brev11 positions) ----
        {
            float2 v[16];
            if (tid < 128) {
#pragma unroll
                for (int j = 0; j < 16; j++) v[j] = x[SIDX(tid + 128 * j)];
                fwd16(v, tw2048(tid));
#pragma unroll
                for (int j = 0; j < 16; j++) x[SIDX(tid + 128 * j)] = v[j];
            }
            __syncthreads();
            if (tid < 128) {
                int baseB = ((tid >> 3) << 7) + (tid & 7);
#pragma unroll
                for (int j = 0; j < 16; j++) v[j] = x[SIDX(baseB + 8 * j)];
                fwd16(v, tw2048((tid & 7) << 4));
#pragma unroll
                for (int j = 0; j < 16; j++) x[SIDX(baseB + 8 * j)] = v[j];
            }
            __syncthreads();
        }
        {
            float2 v8[8];
#pragma unroll
            for (int j = 0; j < 8; j++) v8[j] = x[SIDX(8 * tid + j)];
            fwd8(v8, make_float2(1.f, 0.f));
            // ---- ODD half of K^: position q=8*tid+j -> kf[(q&15)*256+128+(q>>4)]
#pragma unroll
            for (int j = 0; j < 8; j++) {
                int q = 8 * tid + j;
                kf[(q & 15) * 256 + 128 + (q >> 4)] = v8[j];
            }
        }

        // release
        __syncthreads();
        if (tid == 0) {
            __threadfence();
            atomicExch(&d_flags[h], 1);
        }
    } else {
        // ================= CONV branch =================
        const int i  = blockIdx.x - HCH;
        const int hp = i & (HCH / 2 - 1);      // 0..255
        const int bp = i >> 8;                 // 0..3
        const int t  = threadIdx.x;

        if (t == 0) {
            while (atomicAdd(&d_flags[2 * hp], 0) == 0) __nanosleep(200);
            while (atomicAdd(&d_flags[2 * hp + 1], 0) == 0) __nanosleep(200);
            __threadfence();
        }
        __syncthreads();

        const float2* ua2 = (const float2*)(u + (size_t)(2 * bp) * LSEQ * HCH) + hp;
        const float2* ub2 = (const float2*)(u + (size_t)(2 * bp + 1) * LSEQ * HCH) + hp;

        float2 v[16], z1[8], y0[8];
#pragma unroll
        for (int j = 0; j < 8; j++) {
            size_t idx = (size_t)(t + 256 * j) * (HCH / 2);
            float2 la = ua2[idx];
            float2 lb = ub2[idx];
            v[j]  = make_float2(la.x, lb.x);   // channel 2hp:   b0 + i*b1
            z1[j] = make_float2(la.y, lb.y);   // channel 2hp+1: b0 + i*b1
        }
        // v[8..15] implicitly zero (fwd16z)

        const float2 w1  = tw4096(t);
        const float2 wp2 = tw4096((t & 15) << 4);
        const int base2  = ((t >> 4) << 8) + (t & 15);

        fft_conv_4096(v, x, t, base2, w1, wp2, d_Kf + (size_t)(2 * hp) * NFFT);
#pragma unroll
        for (int j = 0; j < 8; j++) y0[j] = v[j];

#pragma unroll
        for (int j = 0; j < 8; j++) v[j] = z1[j];
        fft_conv_4096(v, x, t, base2, w1, wp2, d_Kf + (size_t)(2 * hp + 1) * NFFT);

        const float D0  = D[2 * hp];
        const float D1  = D[2 * hp + 1];
        const float inv = 1.0f / (float)NFFT;
        float2* ya2 = (float2*)(y + (size_t)(2 * bp) * LSEQ * HCH) + hp;
        float2* yb2 = (float2*)(y + (size_t)(2 * bp + 1) * LSEQ * HCH) + hp;
#pragma unroll
        for (int j = 0; j < 8; j++) {
            size_t idx = (size_t)(t + 256 * j) * (HCH / 2);
            float2 la = ua2[idx];
            float2 lb = ub2[idx];
            float2 oa, ob;
            oa.x = fmaf(y0[j].x, inv, la.x * D0);
            oa.y = fmaf(v[j].x,  inv, la.y * D1);
            ob.x = fmaf(y0[j].y, inv, lb.x * D0);
            ob.y = fmaf(v[j].y,  inv, lb.y * D1);
            ya2[idx] = oa;
            yb2[idx] = ob;
        }
    }
}

// ---------------------------------------------------------------------------
extern "C" void kernel_launch(void* const* d_in, const int* in_sizes, int n_in,
                              void* d_out, int out_size) {
    const float* u   = (const float*)d_in[0];
    const float* Lr  = (const float*)d_in[1];
    const float* Li  = (const float*)d_in[2];
    const float* Pr  = (const float*)d_in[3];
    const float* Pi  = (const float*)d_in[4];
    const float* Br  = (const float*)d_in[5];
    const float* Bi  = (const float*)d_in[6];
    const float* Cr  = (const float*)d_in[7];
    const float* Ci  = (const float*)d_in[8];
    const float* ldt = (const float*)d_in[9];
    const float* D   = (const float*)d_in[10];
    float* y = (float*)d_out;

    const size_t smem = (size_t)SPAD * sizeof(float2);   // 34816 B

    zero_flags<<<1, HCH>>>();
    fused_kernel<<<HCH + (HCH / 2) * (BS / 2), 256, smem>>>(
        u, Lr, Li, Pr, Pi, Br, Bi, Cr, Ci, ldt, D, y);
}